// round 3
// baseline (speedup 1.0000x reference)
#include <cuda_runtime.h>

#define N_NODES 10000
#define IN_CH   128
#define OUT_CH  64
#define NSTEP   16
#define E_EDGES 320000
#define K_SEL   (E_EDGES/2)
#define NB      16
#define CAND_CAP 65536
#define KPT     3

// ---------------- device scratch ----------------
__device__ float         g_beta[N_NODES*NSTEP];
__device__ float         g_mean_beta[N_NODES];
__device__ float         g_val[N_NODES*OUT_CH];
__device__ float         g_denom[N_NODES*NSTEP];
__device__ float         g_Weff[IN_CH*16];
__device__ float         g_beff[16];
__device__ unsigned int  g_hist16[65536];
__device__ int           g_sel[K_SEL];
__device__ int           g_sel_cnt;
__device__ unsigned int  g_candA_key[CAND_CAP];
__device__ int           g_candA_idx[CAND_CAP];
__device__ unsigned int  g_candB_key[CAND_CAP];
__device__ int           g_candB_idx[CAND_CAP];
__device__ int           g_cand_cnt;
__device__ unsigned int  g_B;
__device__ int           g_R;
__device__ unsigned int  g_bar_cnt, g_bar_gen;

__device__ __forceinline__ unsigned int fxform(float f) {
    unsigned int u = __float_as_uint(f);
    return (u & 0x80000000u) ? ~u : (u | 0x80000000u);
}

__device__ __forceinline__ void gbar() {
    __syncthreads();
    if (threadIdx.x == 0) {
        volatile unsigned int* gen_p = &g_bar_gen;
        unsigned int gen = *gen_p;
        __threadfence();
        if (atomicAdd(&g_bar_cnt, 1u) == gridDim.x - 1) {
            g_bar_cnt = 0;
            __threadfence();
            *gen_p = gen + 1u;
        } else {
            while (*gen_p == gen) { }
        }
        __threadfence();
    }
    __syncthreads();
}

// ---------------- precontract Wi's p_t-half with p_t ----------------
__global__ void weff_kernel(const float* __restrict__ Wi,
                            const float* __restrict__ bi,
                            const float* __restrict__ p_t) {
    int t = blockIdx.x * blockDim.x + threadIdx.x;
    if (t < IN_CH*16) {
        int c = t >> 4, s = t & 15;
        const float* w = Wi + c*512 + s*32 + 16;
        const float* p = p_t + s*16;
        float sum = 0.f;
        #pragma unroll
        for (int k = 0; k < 16; k++) sum = fmaf(w[k], p[k], sum);
        g_Weff[c*16 + s] = sum;
    }
    if (t < 16) {
        const float* b = bi + t*32 + 16;
        const float* p = p_t + t*16;
        float sum = 0.f;
        #pragma unroll
        for (int k = 0; k < 16; k++) sum = fmaf(b[k], p[k], sum);
        g_beff[t] = sum;
    }
}

// ---------------- node GEMM (336 cols) + beta + init ----------------
__global__ __launch_bounds__(256) void node_kernel(
    const float* __restrict__ x,
    const float* __restrict__ Wv, const float* __restrict__ bv,
    const float* __restrict__ Wi, const float* __restrict__ bi,
    const float* __restrict__ mw,
    float* __restrict__ out)
{
    __shared__ float xsT[IN_CH][NB];       // 8KB
    __shared__ float hwS[NB][16][17];      // 17.4KB : only low-16 of each 32-group
    __shared__ float effS[NB][16];         // 1KB
    __shared__ float betaS[NB][17];

    int tid   = threadIdx.x;
    int node0 = blockIdx.x * NB;

    // folded init (consumed by select_kernel)
    {
        int i = blockIdx.x * 256 + tid;
        int stride = gridDim.x * 256;
        for (int idx = i; idx < N_NODES*OUT_CH; idx += stride) out[idx] = 0.0f;
        for (int idx = i; idx < N_NODES*NSTEP; idx += stride) g_denom[idx] = 0.0f;
        for (int idx = i; idx < 65536; idx += stride) g_hist16[idx] = 0u;
        if (i == 0) { g_sel_cnt = 0; g_cand_cnt = 0; }
    }

    for (int idx = tid; idx < NB*IN_CH; idx += 256) {
        int n = idx >> 7, k = idx & 127;
        xsT[k][n] = x[(node0 + n)*IN_CH + k];
    }
    __syncthreads();

    const int s0 = tid >> 4, k0 = tid & 15;
    const int colA = s0*32 + k0;           // Wi low-half column

    const float* pB = Wv;  int strideB = 0; bool hasB = false;
    if (tid < 64)       { pB = Wv + tid;            strideB = 64; hasB = true; }
    else if (tid < 80)  { pB = g_Weff + (tid - 64); strideB = 16; hasB = true; }

    float acc0[NB], acc1[NB];
    #pragma unroll
    for (int n = 0; n < NB; n++) { acc0[n] = 0.f; acc1[n] = 0.f; }

    for (int k = 0; k < IN_CH; k++) {
        float w0 = Wi[k*512 + colA];
        float w1 = hasB ? pB[k*strideB] : 0.0f;
        #pragma unroll
        for (int n = 0; n < NB; n++) {
            float xv = xsT[k][n];
            acc0[n] = fmaf(xv, w0, acc0[n]);
            acc1[n] = fmaf(xv, w1, acc1[n]);
        }
    }

    {
        float b0 = bi[colA];
        #pragma unroll
        for (int n = 0; n < NB; n++) hwS[n][s0][k0] = acc0[n] + b0;
    }
    if (tid < 64) {
        float bvv = bv[tid];
        #pragma unroll
        for (int n = 0; n < NB; n++) {
            float v = acc1[n] + bvv;
            g_val[(node0 + n)*64 + tid] = v > 0.f ? v : 0.f;
        }
    } else if (tid < 80) {
        int s = tid - 64;
        #pragma unroll
        for (int n = 0; n < NB; n++) effS[n][s] = acc1[n];
    }
    __syncthreads();

    {
        int n = tid >> 4, s = tid & 15;
        const float* mwrow = mw + (node0 + n)*16;
        float sum = 0.f;
        #pragma unroll
        for (int k = 0; k < 16; k++) sum = fmaf(hwS[n][s][k], mwrow[k], sum);
        float b = (sum + effS[n][s] + g_beff[s]) * (1.0f/32.0f);
        betaS[n][s] = b;
        g_beta[(node0 + n)*NSTEP + s] = b;
    }
    __syncthreads();
    if (tid < NB) {
        float s = 0.f;
        #pragma unroll
        for (int k = 0; k < NSTEP; k++) s += betaS[tid][k];
        g_mean_beta[node0 + tid] = s * (1.0f/NSTEP);
    }
}

// ---------------- persistent select + softmax-accumulate ----------------
__global__ __launch_bounds__(1024, 1) void select_kernel(
    const int* __restrict__ ei, const float* __restrict__ ew,
    float* __restrict__ out)
{
    const int T    = gridDim.x * blockDim.x;
    const int gtid = blockIdx.x * blockDim.x + threadIdx.x;
    const int lane = threadIdx.x & 31;

    __shared__ unsigned int s_scan[1024];
    __shared__ unsigned int s_key[4096];
    __shared__ int          s_idx[4096];
    __shared__ unsigned int s_h[256];
    __shared__ int s_cnt, sh_b2, sh_R2;

    // ---- keys (registers) + 16-bit histogram (warp-aggregated atomics) ----
    unsigned int keys[KPT];
    #pragma unroll
    for (int j = 0; j < KPT; j++) {
        int e = gtid + j*T;
        if (e < E_EDGES) {
            int dst = ei[E_EDGES + e];
            float s = ew[e] * g_mean_beta[dst];
            s += 0.0f;                                 // -0 -> +0
            keys[j] = fxform(s);
            unsigned int bin = keys[j] >> 16;
            unsigned int m = __match_any_sync(__activemask(), bin);
            int ldr = __ffs(m) - 1;
            if (lane == ldr) atomicAdd(&g_hist16[bin], __popc(m));
        }
    }
    gbar();

    // ---- scan: find threshold bucket B and residual R (block 0) ----
    if (blockIdx.x == 0) {
        int base = threadIdx.x * 64;
        unsigned int sum = 0;
        for (int j = 0; j < 64; j++) sum += __ldcg(&g_hist16[base + j]);
        s_scan[threadIdx.x] = sum;
        __syncthreads();
        for (int off = 1; off < 1024; off <<= 1) {
            unsigned int v = s_scan[threadIdx.x];
            unsigned int a = (threadIdx.x + off < 1024) ? s_scan[threadIdx.x + off] : 0u;
            __syncthreads();
            s_scan[threadIdx.x] = v + a;
            __syncthreads();
        }
        unsigned int incl = s_scan[threadIdx.x];
        unsigned int excl = incl - sum;
        if (excl < (unsigned)K_SEL && incl >= (unsigned)K_SEL) {
            unsigned int cum = excl;
            for (int b = 63; b >= 0; b--) {
                unsigned int c = __ldcg(&g_hist16[base + b]);
                if (cum + c >= (unsigned)K_SEL) {
                    g_B = (unsigned)(base + b);
                    g_R = K_SEL - (int)cum;
                    break;
                }
                cum += c;
            }
        }
    }
    gbar();

    // ---- flag: compact definite winners; collect threshold-bucket candidates ----
    {
        unsigned int B = *(volatile unsigned int*)&g_B;
        #pragma unroll
        for (int j = 0; j < KPT; j++) {
            int e = gtid + j*T;
            if (e < E_EDGES) {
                unsigned int t16 = keys[j] >> 16;
                if (t16 > B) {
                    int p = atomicAdd(&g_sel_cnt, 1);
                    g_sel[p] = e;
                } else if (t16 == B) {
                    int p = atomicAdd(&g_cand_cnt, 1);
                    if (p < CAND_CAP) { g_candA_key[p] = keys[j]; g_candA_idx[p] = e; }
                }
            }
        }
    }
    gbar();

    // ---- resolve candidates exactly in block 0 ----
    if (blockIdx.x == 0) {
        int C = *(volatile int*)&g_cand_cnt; if (C > CAND_CAP) C = CAND_CAP;
        int R = *(volatile int*)&g_R;
        unsigned int* ck = g_candA_key; int* ci = g_candA_idx;
        unsigned int* ck2 = g_candB_key; int* ci2 = g_candB_idx;
        int shift = 8;
        while (C > 4096 && shift >= 0) {          // (practically never taken)
            if (threadIdx.x < 256) s_h[threadIdx.x] = 0u;
            __syncthreads();
            for (int i = threadIdx.x; i < C; i += 1024)
                atomicAdd(&s_h[(__ldcg(&ck[i]) >> shift) & 255u], 1u);
            __syncthreads();
            if (threadIdx.x == 0) {
                unsigned int cum = 0;
                for (int b = 255; b >= 0; b--) {
                    unsigned int c = s_h[b];
                    if (cum + c >= (unsigned)R) { sh_b2 = b; sh_R2 = R - (int)cum; break; }
                    cum += c;
                }
                s_cnt = 0;
            }
            __syncthreads();
            int b2 = sh_b2;
            for (int i = threadIdx.x; i < C; i += 1024) {
                unsigned int k = __ldcg(&ck[i]); int idx = __ldcg(&ci[i]);
                int v = (int)((k >> shift) & 255u);
                if (v > b2) { int p = atomicAdd(&g_sel_cnt, 1); g_sel[p] = idx; }
                else if (v == b2) { int p = atomicAdd(&s_cnt, 1); ck2[p] = k; ci2[p] = idx; }
            }
            __syncthreads();
            C = s_cnt; R = sh_R2;
            unsigned int* tk = ck; ck = ck2; ck2 = tk;
            int* ti = ci; ci = ci2; ci2 = ti;
            shift -= 8;
            __syncthreads();
        }
        if (C > 4096) C = 4096;
        for (int i = threadIdx.x; i < C; i += 1024) { s_key[i] = __ldcg(&ck[i]); s_idx[i] = __ldcg(&ci[i]); }
        __syncthreads();
        for (int i = threadIdx.x; i < C; i += 1024) {
            unsigned int ki = s_key[i]; int xi = s_idx[i];
            int rank = 0;
            for (int j2 = 0; j2 < C; j2++) {
                unsigned int kj = s_key[j2];
                rank += (kj > ki) || (kj == ki && s_idx[j2] < xi);
            }
            if (rank < R) { int p = atomicAdd(&g_sel_cnt, 1); g_sel[p] = xi; }
        }
    }
    gbar();

    // ---- softmax numerator + denominator over compacted edges ----
    {
        const int total = K_SEL * 16;
        for (int t = gtid; t < total; t += T) {
            int e = __ldcg(&g_sel[t >> 4]);
            int l = t & 15;
            int src = ei[e];
            int dst = ei[E_EDGES + e];
            float g  = g_beta[dst*NSTEP + l] * ew[e];
            float ex = __expf(g);
            atomicAdd(&g_denom[src*NSTEP + l], ex);
            const float4 v = *reinterpret_cast<const float4*>(&g_val[dst*64 + l*4]);
            float* o = out + src*64 + l*4;
            atomicAdd(o + 0, v.x * ex);
            atomicAdd(o + 1, v.y * ex);
            atomicAdd(o + 2, v.z * ex);
            atomicAdd(o + 3, v.w * ex);
        }
    }
    gbar();

    // ---- final divide ----
    for (int i = gtid; i < N_NODES*OUT_CH; i += T) {
        int n = i >> 6;
        int s = (i >> 2) & 15;
        float d = __ldcg(&g_denom[n*NSTEP + s]);
        out[i] = __ldcg(&out[i]) / (d + 1e-16f);
    }
}

// ---------------- launch ----------------
extern "C" void kernel_launch(void* const* d_in, const int* in_sizes, int n_in,
                              void* d_out, int out_size) {
    const float* x   = (const float*)d_in[0];
    const float* p_t = (const float*)d_in[1];
    const int*   ei  = (const int*)  d_in[2];
    const float* ew  = (const float*)d_in[3];
    const float* Wv  = (const float*)d_in[4];
    const float* bv  = (const float*)d_in[5];
    const float* Wi  = (const float*)d_in[6];
    const float* bi  = (const float*)d_in[7];
    const float* mw  = (const float*)d_in[8];
    float* out = (float*)d_out;

    int dev = 0, sms = 148;
    cudaGetDevice(&dev);
    cudaDeviceGetAttribute(&sms, cudaDevAttrMultiProcessorCount, dev);
    int grid_p = sms;
    int min_grid = (E_EDGES + KPT*1024 - 1) / (KPT*1024);   // 105
    if (grid_p < min_grid) grid_p = min_grid;

    weff_kernel<<<8, 256>>>(Wi, bi, p_t);
    node_kernel<<<N_NODES/NB, 256>>>(x, Wv, bv, Wi, bi, mw, out);
    select_kernel<<<grid_p, 1024>>>(ei, ew, out);
}

// round 4
// speedup vs baseline: 1.0315x; 1.0315x over previous
#include <cuda_runtime.h>

#define N_NODES 10000
#define IN_CH   128
#define OUT_CH  64
#define NSTEP   16
#define E_EDGES 320000
#define K_SEL   (E_EDGES/2)
#define NB      16
#define CAND_CAP 65536
#define KPT     3

// ---------------- device scratch ----------------
__device__ float         g_beta[N_NODES*NSTEP];
__device__ float         g_mean_beta[N_NODES];
__device__ float         g_val[N_NODES*OUT_CH];
__device__ float         g_Weff[IN_CH*16];
__device__ float         g_beff[16];
__device__ unsigned int  g_hist16[65536];
__device__ int           g_srcCnt[N_NODES];
__device__ int           g_srcBase[N_NODES];
__device__ int           g_srcCur[N_NODES];
__device__ int           g_sDst[K_SEL];
__device__ float         g_sEw[K_SEL];
__device__ unsigned int  g_candK[CAND_CAP];
__device__ int           g_candE[CAND_CAP];
__device__ unsigned char g_candW[CAND_CAP];
__device__ int           g_cand_cnt;
__device__ unsigned int  g_B;
__device__ int           g_R;
__device__ unsigned int  g_bar_cnt, g_bar_gen;

__device__ __forceinline__ unsigned int fxform(float f) {
    unsigned int u = __float_as_uint(f);
    return (u & 0x80000000u) ? ~u : (u | 0x80000000u);
}

__device__ __forceinline__ void gbar() {
    __syncthreads();
    if (threadIdx.x == 0) {
        volatile unsigned int* gen_p = &g_bar_gen;
        unsigned int gen = *gen_p;
        __threadfence();
        if (atomicAdd(&g_bar_cnt, 1u) == gridDim.x - 1) {
            g_bar_cnt = 0;
            __threadfence();
            *gen_p = gen + 1u;
        } else {
            while (*gen_p == gen) { }
        }
        __threadfence();
    }
    __syncthreads();
}

// ---------------- prep: zero scratch + precontract Wi upper half with p_t ----------------
__global__ void prep_kernel(const float* __restrict__ Wi,
                            const float* __restrict__ bi,
                            const float* __restrict__ p_t) {
    int t = blockIdx.x * blockDim.x + threadIdx.x;
    int stride = gridDim.x * blockDim.x;
    for (int i = t; i < 65536; i += stride) g_hist16[i] = 0u;
    for (int i = t; i < N_NODES; i += stride) g_srcCnt[i] = 0;
    if (t == 0) g_cand_cnt = 0;
    if (t < IN_CH*16) {
        int c = t >> 4, s = t & 15;
        const float* w = Wi + c*512 + s*32 + 16;
        const float* p = p_t + s*16;
        float sum = 0.f;
        #pragma unroll
        for (int k = 0; k < 16; k++) sum = fmaf(w[k], p[k], sum);
        g_Weff[c*16 + s] = sum;
    }
    if (t < 16) {
        const float* b = bi + t*32 + 16;
        const float* p = p_t + t*16;
        float sum = 0.f;
        #pragma unroll
        for (int k = 0; k < 16; k++) sum = fmaf(b[k], p[k], sum);
        g_beff[t] = sum;
    }
}

// ---------------- node GEMM (336 effective cols) + beta ----------------
__global__ __launch_bounds__(256) void node_kernel(
    const float* __restrict__ x,
    const float* __restrict__ Wv, const float* __restrict__ bv,
    const float* __restrict__ Wi, const float* __restrict__ bi,
    const float* __restrict__ mw)
{
    __shared__ float4 xs4[NB][32];         // x tile as float4 along k, 8KB
    __shared__ float  hwS[NB][16][17];
    __shared__ float  effS[NB][16];
    __shared__ float  betaS[NB][17];

    int tid   = threadIdx.x;
    int node0 = blockIdx.x * NB;

    for (int idx = tid; idx < NB*32; idx += 256) {
        int n = idx >> 5, k4 = idx & 31;
        xs4[n][k4] = reinterpret_cast<const float4*>(x)[(node0 + n)*32 + k4];
    }
    __syncthreads();

    const int s0 = tid >> 4, k0 = tid & 15;
    const int colA = s0*32 + k0;

    const float* pB = Wv;  int strideB = 0; bool hasB = false;
    if (tid < 64)       { pB = Wv + tid;            strideB = 64; hasB = true; }
    else if (tid < 80)  { pB = g_Weff + (tid - 64); strideB = 16; hasB = true; }

    float acc0[NB], acc1[NB];
    #pragma unroll
    for (int n = 0; n < NB; n++) { acc0[n] = 0.f; acc1[n] = 0.f; }

    for (int k4 = 0; k4 < 32; k4++) {
        int k = k4 * 4;
        float w00 = Wi[(k+0)*512 + colA];
        float w01 = Wi[(k+1)*512 + colA];
        float w02 = Wi[(k+2)*512 + colA];
        float w03 = Wi[(k+3)*512 + colA];
        float w10 = 0.f, w11 = 0.f, w12 = 0.f, w13 = 0.f;
        if (hasB) {
            w10 = pB[(k+0)*strideB]; w11 = pB[(k+1)*strideB];
            w12 = pB[(k+2)*strideB]; w13 = pB[(k+3)*strideB];
        }
        #pragma unroll
        for (int n = 0; n < NB; n++) {
            float4 xv = xs4[n][k4];
            acc0[n] = fmaf(xv.x, w00, acc0[n]);
            acc0[n] = fmaf(xv.y, w01, acc0[n]);
            acc0[n] = fmaf(xv.z, w02, acc0[n]);
            acc0[n] = fmaf(xv.w, w03, acc0[n]);
            acc1[n] = fmaf(xv.x, w10, acc1[n]);
            acc1[n] = fmaf(xv.y, w11, acc1[n]);
            acc1[n] = fmaf(xv.z, w12, acc1[n]);
            acc1[n] = fmaf(xv.w, w13, acc1[n]);
        }
    }

    {
        float b0 = bi[colA];
        #pragma unroll
        for (int n = 0; n < NB; n++) hwS[n][s0][k0] = acc0[n] + b0;
    }
    if (tid < 64) {
        float bvv = bv[tid];
        #pragma unroll
        for (int n = 0; n < NB; n++) {
            float v = acc1[n] + bvv;
            g_val[(node0 + n)*64 + tid] = v > 0.f ? v : 0.f;
        }
    } else if (tid < 80) {
        int s = tid - 64;
        #pragma unroll
        for (int n = 0; n < NB; n++) effS[n][s] = acc1[n];
    }
    __syncthreads();

    {
        int n = tid >> 4, s = tid & 15;
        const float* mwrow = mw + (node0 + n)*16;
        float sum = 0.f;
        #pragma unroll
        for (int k = 0; k < 16; k++) sum = fmaf(hwS[n][s][k], mwrow[k], sum);
        float b = (sum + effS[n][s] + g_beff[s]) * (1.0f/32.0f);
        betaS[n][s] = b;
        g_beta[(node0 + n)*NSTEP + s] = b;
    }
    __syncthreads();
    if (tid < NB) {
        float s = 0.f;
        #pragma unroll
        for (int k = 0; k < NSTEP; k++) s += betaS[tid][k];
        g_mean_beta[node0 + tid] = s * (1.0f/NSTEP);
    }
}

// ---------------- persistent: select + counting sort by src + atomic-free accumulate ----------------
__global__ __launch_bounds__(1024, 1) void select_kernel(
    const int* __restrict__ ei, const float* __restrict__ ew,
    float* __restrict__ out)
{
    const int T    = gridDim.x * blockDim.x;
    const int gtid = blockIdx.x * blockDim.x + threadIdx.x;
    const int lane = threadIdx.x & 31;
    const unsigned FULL = 0xFFFFFFFFu;

    __shared__ unsigned int s_scan[1024];
    __shared__ unsigned int s_key[4096];
    __shared__ int          s_idx[4096];

    // ---- P0: keys + dsts into registers, 16-bit histogram ----
    unsigned int keys[KPT];
    int dsts[KPT];
    #pragma unroll
    for (int j = 0; j < KPT; j++) {
        int e = gtid + j*T;
        if (e < E_EDGES) {
            int dst = ei[E_EDGES + e];
            dsts[j] = dst;
            float s = ew[e] * g_mean_beta[dst];
            s += 0.0f;                                 // -0 -> +0
            keys[j] = fxform(s);
            unsigned int bin = keys[j] >> 16;
            unsigned int m = __match_any_sync(__activemask(), bin);
            int ldr = __ffs(m) - 1;
            if (lane == ldr) atomicAdd(&g_hist16[bin], __popc(m));
        }
    }
    gbar();

    // ---- P1: threshold bucket B + residual R (block 0) ----
    if (blockIdx.x == 0) {
        int base = threadIdx.x * 64;
        unsigned int sum = 0;
        for (int j = 0; j < 64; j++) sum += __ldcg(&g_hist16[base + j]);
        s_scan[threadIdx.x] = sum;
        __syncthreads();
        for (int off = 1; off < 1024; off <<= 1) {
            unsigned int v = s_scan[threadIdx.x];
            unsigned int a = (threadIdx.x + off < 1024) ? s_scan[threadIdx.x + off] : 0u;
            __syncthreads();
            s_scan[threadIdx.x] = v + a;
            __syncthreads();
        }
        unsigned int incl = s_scan[threadIdx.x];
        unsigned int excl = incl - sum;
        if (excl < (unsigned)K_SEL && incl >= (unsigned)K_SEL) {
            unsigned int cum = excl;
            for (int b = 63; b >= 0; b--) {
                unsigned int c = __ldcg(&g_hist16[base + b]);
                if (cum + c >= (unsigned)K_SEL) {
                    g_B = (unsigned)(base + b);
                    g_R = K_SEL - (int)cum;
                    break;
                }
                cum += c;
            }
        }
    }
    gbar();

    // ---- P2: count definite winners per src; collect threshold-bucket candidates ----
    unsigned int wbits = 0;
    {
        unsigned int B = *(volatile unsigned int*)&g_B;
        #pragma unroll
        for (int j = 0; j < KPT; j++) {
            int e = gtid + j*T;
            if (e < E_EDGES) {
                unsigned int t16 = keys[j] >> 16;
                if (t16 > B) {
                    wbits |= 1u << j;
                    atomicAdd(&g_srcCnt[ei[e]], 1);
                } else if (t16 == B) {
                    int p = atomicAdd(&g_cand_cnt, 1);
                    if (p < CAND_CAP) { g_candK[p] = keys[j]; g_candE[p] = e; }
                }
            }
        }
    }
    gbar();

    // ---- P3 (block 0): resolve candidates exactly, then prefix-sum src counts ----
    if (blockIdx.x == 0) {
        int C = *(volatile int*)&g_cand_cnt; if (C > CAND_CAP) C = CAND_CAP;
        int R = *(volatile int*)&g_R;
        if (C <= 4096) {
            for (int i = threadIdx.x; i < C; i += 1024) {
                s_key[i] = __ldcg(&g_candK[i]); s_idx[i] = __ldcg(&g_candE[i]);
            }
            __syncthreads();
            for (int i = threadIdx.x; i < C; i += 1024) {
                unsigned int ki = s_key[i]; int xi = s_idx[i];
                int rank = 0;
                for (int j = 0; j < C; j++) {
                    unsigned int kj = s_key[j];
                    rank += (kj > ki) || (kj == ki && s_idx[j] < xi);
                }
                unsigned char w = (rank < R) ? 1 : 0;
                g_candW[i] = w;
                if (w) atomicAdd(&g_srcCnt[ei[xi]], 1);
            }
        } else {  // pathological fallback (correct, slow, practically never taken)
            for (int i = threadIdx.x; i < C; i += 1024) {
                unsigned int ki = __ldcg(&g_candK[i]); int xi = __ldcg(&g_candE[i]);
                int rank = 0;
                for (int j = 0; j < C; j++) {
                    unsigned int kj = __ldcg(&g_candK[j]);
                    rank += (kj > ki) || (kj == ki && __ldcg(&g_candE[j]) < xi);
                }
                unsigned char w = (rank < R) ? 1 : 0;
                g_candW[i] = w;
                if (w) atomicAdd(&g_srcCnt[ei[xi]], 1);
            }
        }
        __threadfence();
        __syncthreads();
        // exclusive prefix over g_srcCnt (10 nodes per thread)
        int nbase = threadIdx.x * 10;
        int lsum = 0;
        for (int q = 0; q < 10; q++) {
            int n = nbase + q;
            if (n < N_NODES) lsum += __ldcg(&g_srcCnt[n]);
        }
        s_scan[threadIdx.x] = (unsigned)lsum;
        __syncthreads();
        for (int off = 1; off < 1024; off <<= 1) {
            unsigned int v = s_scan[threadIdx.x];
            unsigned int a = (threadIdx.x >= off) ? s_scan[threadIdx.x - off] : 0u;
            __syncthreads();
            s_scan[threadIdx.x] = v + a;
            __syncthreads();
        }
        int run = (int)s_scan[threadIdx.x] - lsum;
        for (int q = 0; q < 10; q++) {
            int n = nbase + q;
            if (n < N_NODES) {
                int c = __ldcg(&g_srcCnt[n]);
                g_srcBase[n] = run;
                g_srcCur[n]  = run;
                run += c;
            }
        }
    }
    gbar();

    // ---- P4: scatter winners (dst, ew) into src-sorted arrays ----
    #pragma unroll
    for (int j = 0; j < KPT; j++) {
        if ((wbits >> j) & 1u) {
            int e = gtid + j*T;
            int src = ei[e];
            int pos = atomicAdd(&g_srcCur[src], 1);
            g_sDst[pos] = dsts[j];
            g_sEw[pos]  = ew[e];
        }
    }
    if (blockIdx.x == 0) {
        int C = *(volatile int*)&g_cand_cnt; if (C > CAND_CAP) C = CAND_CAP;
        for (int i = threadIdx.x; i < C; i += 1024) {
            if (g_candW[i]) {
                int e = g_candE[i];
                int src = ei[e];
                int pos = atomicAdd(&g_srcCur[src], 1);
                g_sDst[pos] = ei[E_EDGES + e];
                g_sEw[pos]  = ew[e];
            }
        }
    }
    gbar();

    // ---- P5: warp-per-src accumulate, atomic-free, direct out write ----
    {
        int nwarps = T >> 5;
        int gw = gtid >> 5;
        int s0 = lane >> 2;            // ex source lane for channel c=lane
        int s1 = 8 + (lane >> 2);      // ex source lane for channel c=lane+32
        for (int src = gw; src < N_NODES; src += nwarps) {
            int cnt  = __ldcg(&g_srcCnt[src]);
            int base = __ldcg(&g_srcBase[src]);
            float a0 = 0.f, a1 = 0.f, ds = 0.f;
            for (int i = 0; i < cnt; i++) {
                int   dst = __ldcg(&g_sDst[base + i]);
                float w   = __ldcg(&g_sEw[base + i]);
                float ex = 0.f;
                if (lane < 16) ex = __expf(g_beta[dst*NSTEP + lane] * w);
                float e0 = __shfl_sync(FULL, ex, s0);
                float e1 = __shfl_sync(FULL, ex, s1);
                float v0 = g_val[dst*64 + lane];
                float v1 = g_val[dst*64 + 32 + lane];
                a0 = fmaf(e0, v0, a0);
                a1 = fmaf(e1, v1, a1);
                ds += ex;
            }
            float d0 = __shfl_sync(FULL, ds, s0) + 1e-16f;
            float d1 = __shfl_sync(FULL, ds, s1) + 1e-16f;
            out[src*64 + lane]      = a0 / d0;
            out[src*64 + 32 + lane] = a1 / d1;
        }
    }
}

// ---------------- launch ----------------
extern "C" void kernel_launch(void* const* d_in, const int* in_sizes, int n_in,
                              void* d_out, int out_size) {
    const float* x   = (const float*)d_in[0];
    const float* p_t = (const float*)d_in[1];
    const int*   ei  = (const int*)  d_in[2];
    const float* ew  = (const float*)d_in[3];
    const float* Wv  = (const float*)d_in[4];
    const float* bv  = (const float*)d_in[5];
    const float* Wi  = (const float*)d_in[6];
    const float* bi  = (const float*)d_in[7];
    const float* mw  = (const float*)d_in[8];
    float* out = (float*)d_out;

    int dev = 0, sms = 148;
    cudaGetDevice(&dev);
    cudaDeviceGetAttribute(&sms, cudaDevAttrMultiProcessorCount, dev);
    int grid_p = sms;
    int min_grid = (E_EDGES + KPT*1024 - 1) / (KPT*1024);
    if (grid_p < min_grid) grid_p = min_grid;

    prep_kernel<<<sms, 256>>>(Wi, bi, p_t);
    node_kernel<<<N_NODES/NB, 256>>>(x, Wv, bv, Wi, bi, mw);
    select_kernel<<<grid_p, 1024>>>(ei, ew, out);
}

// round 5
// speedup vs baseline: 1.1774x; 1.1414x over previous
#include <cuda_runtime.h>

#define N_NODES 10000
#define IN_CH   128
#define OUT_CH  64
#define NSTEP   16
#define E_EDGES 320000
#define K_SEL   (E_EDGES/2)
#define NB      16
#define CAND_CAP 65536

// ---------------- device scratch ----------------
__device__ float         g_beta[N_NODES*NSTEP];
__device__ float         g_mean_beta[N_NODES];
__device__ float         g_val[N_NODES*OUT_CH];
__device__ float         g_Weff[IN_CH*16];
__device__ float         g_beff[16];
__device__ unsigned int  g_keys[E_EDGES];
__device__ unsigned char g_flags[E_EDGES];
__device__ unsigned int  g_hist16[65536];
__device__ int           g_srcCnt[N_NODES];
__device__ int           g_srcBase[N_NODES];
__device__ int           g_srcCur[N_NODES];
__device__ int           g_sDst[K_SEL];
__device__ float         g_sEw[K_SEL];
__device__ unsigned int  g_candK[CAND_CAP];
__device__ int           g_candE[CAND_CAP];
__device__ int           g_cand_cnt;
__device__ unsigned int  g_B;
__device__ int           g_R;

__device__ __forceinline__ unsigned int fxform(float f) {
    unsigned int u = __float_as_uint(f);
    return (u & 0x80000000u) ? ~u : (u | 0x80000000u);
}

// ---------------- 1. prep: zero scratch + precontract Wi upper halves with p_t ----------------
__global__ void prep_kernel(const float* __restrict__ Wi,
                            const float* __restrict__ bi,
                            const float* __restrict__ p_t) {
    int t = blockIdx.x * blockDim.x + threadIdx.x;
    int stride = gridDim.x * blockDim.x;
    for (int i = t; i < 65536; i += stride) g_hist16[i] = 0u;
    for (int i = t; i < N_NODES; i += stride) g_srcCnt[i] = 0;
    if (t == 0) g_cand_cnt = 0;
    if (t < IN_CH*16) {
        int c = t >> 4, s = t & 15;
        const float* w = Wi + c*512 + s*32 + 16;
        const float* p = p_t + s*16;
        float sum = 0.f;
        #pragma unroll
        for (int k = 0; k < 16; k++) sum = fmaf(w[k], p[k], sum);
        g_Weff[c*16 + s] = sum;
    }
    if (t < 16) {
        const float* b = bi + t*32 + 16;
        const float* p = p_t + t*16;
        float sum = 0.f;
        #pragma unroll
        for (int k = 0; k < 16; k++) sum = fmaf(b[k], p[k], sum);
        g_beff[t] = sum;
    }
}

// ---------------- 2. node GEMM (336 effective cols) + beta ----------------
__global__ __launch_bounds__(256) void node_kernel(
    const float* __restrict__ x,
    const float* __restrict__ Wv, const float* __restrict__ bv,
    const float* __restrict__ Wi, const float* __restrict__ bi,
    const float* __restrict__ mw)
{
    __shared__ float4 xs4[NB][32];
    __shared__ float  hwS[NB][16][17];
    __shared__ float  effS[NB][16];
    __shared__ float  betaS[NB][17];

    int tid   = threadIdx.x;
    int node0 = blockIdx.x * NB;

    for (int idx = tid; idx < NB*32; idx += 256) {
        int n = idx >> 5, k4 = idx & 31;
        xs4[n][k4] = reinterpret_cast<const float4*>(x)[(node0 + n)*32 + k4];
    }
    __syncthreads();

    const int s0 = tid >> 4, k0 = tid & 15;
    const int colA = s0*32 + k0;

    const float* pB = Wv;  int strideB = 0; bool hasB = false;
    if (tid < 64)       { pB = Wv + tid;            strideB = 64; hasB = true; }
    else if (tid < 80)  { pB = g_Weff + (tid - 64); strideB = 16; hasB = true; }

    float acc0[NB], acc1[NB];
    #pragma unroll
    for (int n = 0; n < NB; n++) { acc0[n] = 0.f; acc1[n] = 0.f; }

    for (int k4 = 0; k4 < 32; k4++) {
        int k = k4 * 4;
        float w00 = Wi[(k+0)*512 + colA];
        float w01 = Wi[(k+1)*512 + colA];
        float w02 = Wi[(k+2)*512 + colA];
        float w03 = Wi[(k+3)*512 + colA];
        float w10 = 0.f, w11 = 0.f, w12 = 0.f, w13 = 0.f;
        if (hasB) {
            w10 = pB[(k+0)*strideB]; w11 = pB[(k+1)*strideB];
            w12 = pB[(k+2)*strideB]; w13 = pB[(k+3)*strideB];
        }
        #pragma unroll
        for (int n = 0; n < NB; n++) {
            float4 xv = xs4[n][k4];
            acc0[n] = fmaf(xv.x, w00, acc0[n]);
            acc0[n] = fmaf(xv.y, w01, acc0[n]);
            acc0[n] = fmaf(xv.z, w02, acc0[n]);
            acc0[n] = fmaf(xv.w, w03, acc0[n]);
            acc1[n] = fmaf(xv.x, w10, acc1[n]);
            acc1[n] = fmaf(xv.y, w11, acc1[n]);
            acc1[n] = fmaf(xv.z, w12, acc1[n]);
            acc1[n] = fmaf(xv.w, w13, acc1[n]);
        }
    }

    {
        float b0 = bi[colA];
        #pragma unroll
        for (int n = 0; n < NB; n++) hwS[n][s0][k0] = acc0[n] + b0;
    }
    if (tid < 64) {
        float bvv = bv[tid];
        #pragma unroll
        for (int n = 0; n < NB; n++) {
            float v = acc1[n] + bvv;
            g_val[(node0 + n)*64 + tid] = v > 0.f ? v : 0.f;
        }
    } else if (tid < 80) {
        int s = tid - 64;
        #pragma unroll
        for (int n = 0; n < NB; n++) effS[n][s] = acc1[n];
    }
    __syncthreads();

    {
        int n = tid >> 4, s = tid & 15;
        const float* mwrow = mw + (node0 + n)*16;
        float sum = 0.f;
        #pragma unroll
        for (int k = 0; k < 16; k++) sum = fmaf(hwS[n][s][k], mwrow[k], sum);
        float b = (sum + effS[n][s] + g_beff[s]) * (1.0f/32.0f);
        betaS[n][s] = b;
        g_beta[(node0 + n)*NSTEP + s] = b;
    }
    __syncthreads();
    if (tid < NB) {
        float s = 0.f;
        #pragma unroll
        for (int k = 0; k < NSTEP; k++) s += betaS[tid][k];
        g_mean_beta[node0 + tid] = s * (1.0f/NSTEP);
    }
}

// ---------------- 3. keys + 16-bit histogram ----------------
__global__ void keyhist_kernel(const int* __restrict__ ei, const float* __restrict__ ew) {
    int e = blockIdx.x * blockDim.x + threadIdx.x;
    if (e >= E_EDGES) return;
    int lane = threadIdx.x & 31;
    int dst = ei[E_EDGES + e];
    float s = ew[e] * g_mean_beta[dst];
    s += 0.0f;                                 // -0 -> +0
    unsigned int k = fxform(s);
    g_keys[e] = k;
    unsigned int bin = k >> 16;
    unsigned int m = __match_any_sync(__activemask(), bin);
    int ldr = __ffs(m) - 1;
    if (lane == ldr) atomicAdd(&g_hist16[bin], __popc(m));
}

// ---------------- 4. scan: threshold bucket B + residual R ----------------
__global__ __launch_bounds__(1024) void scanB_kernel() {
    __shared__ unsigned int s_scan[1024];
    int base = threadIdx.x * 64;
    unsigned int sum = 0;
    for (int j = 0; j < 64; j++) sum += g_hist16[base + j];
    s_scan[threadIdx.x] = sum;
    __syncthreads();
    // suffix-sum (descending order scan)
    for (int off = 1; off < 1024; off <<= 1) {
        unsigned int v = s_scan[threadIdx.x];
        unsigned int a = (threadIdx.x + off < 1024) ? s_scan[threadIdx.x + off] : 0u;
        __syncthreads();
        s_scan[threadIdx.x] = v + a;
        __syncthreads();
    }
    unsigned int incl = s_scan[threadIdx.x];
    unsigned int excl = incl - sum;
    if (excl < (unsigned)K_SEL && incl >= (unsigned)K_SEL) {
        unsigned int cum = excl;
        for (int b = 63; b >= 0; b--) {
            unsigned int c = g_hist16[base + b];
            if (cum + c >= (unsigned)K_SEL) {
                g_B = (unsigned)(base + b);
                g_R = K_SEL - (int)cum;
                break;
            }
            cum += c;
        }
    }
}

// ---------------- 5. flag winners + per-src counts + candidates ----------------
__global__ void flagcnt_kernel(const int* __restrict__ ei) {
    int e = blockIdx.x * blockDim.x + threadIdx.x;
    if (e >= E_EDGES) return;
    unsigned int k = g_keys[e];
    unsigned int B = g_B;
    unsigned int t16 = k >> 16;
    unsigned char f = 0;
    if (t16 > B) {
        f = 1;
        atomicAdd(&g_srcCnt[ei[e]], 1);
    } else if (t16 == B) {
        int p = atomicAdd(&g_cand_cnt, 1);
        if (p < CAND_CAP) { g_candK[p] = k; g_candE[p] = e; }
    }
    g_flags[e] = f;
}

// ---------------- 6. resolve ties + prefix-sum src counts ----------------
__global__ __launch_bounds__(1024) void resolve_kernel(const int* __restrict__ ei) {
    __shared__ unsigned int s_key[4096];
    __shared__ int          s_idx[4096];
    __shared__ unsigned int s_scan[1024];

    int C = g_cand_cnt; if (C > CAND_CAP) C = CAND_CAP;
    int R = g_R;
    if (C <= 4096) {
        for (int i = threadIdx.x; i < C; i += 1024) { s_key[i] = g_candK[i]; s_idx[i] = g_candE[i]; }
        __syncthreads();
        for (int i = threadIdx.x; i < C; i += 1024) {
            unsigned int ki = s_key[i]; int xi = s_idx[i];
            int rank = 0;
            for (int j = 0; j < C; j++) {
                unsigned int kj = s_key[j];
                rank += (kj > ki) || (kj == ki && s_idx[j] < xi);
            }
            if (rank < R) {                  // stable: smallest index wins among equals
                g_flags[xi] = 1;
                atomicAdd(&g_srcCnt[ei[xi]], 1);
            }
        }
    } else {                                  // pathological fallback
        for (int i = threadIdx.x; i < C; i += 1024) {
            unsigned int ki = g_candK[i]; int xi = g_candE[i];
            int rank = 0;
            for (int j = 0; j < C; j++) {
                unsigned int kj = g_candK[j];
                rank += (kj > ki) || (kj == ki && g_candE[j] < xi);
            }
            if (rank < R) { g_flags[xi] = 1; atomicAdd(&g_srcCnt[ei[xi]], 1); }
        }
    }
    __threadfence();
    __syncthreads();

    // exclusive prefix over g_srcCnt, 10 nodes/thread
    int nbase = threadIdx.x * 10;
    int lsum = 0;
    int cnts[10];
    #pragma unroll
    for (int q = 0; q < 10; q++) {
        int n = nbase + q;
        cnts[q] = (n < N_NODES) ? g_srcCnt[n] : 0;
        lsum += cnts[q];
    }
    s_scan[threadIdx.x] = (unsigned)lsum;
    __syncthreads();
    for (int off = 1; off < 1024; off <<= 1) {
        unsigned int v = s_scan[threadIdx.x];
        unsigned int a = (threadIdx.x >= off) ? s_scan[threadIdx.x - off] : 0u;
        __syncthreads();
        s_scan[threadIdx.x] = v + a;
        __syncthreads();
    }
    int run = (int)s_scan[threadIdx.x] - lsum;
    #pragma unroll
    for (int q = 0; q < 10; q++) {
        int n = nbase + q;
        if (n < N_NODES) {
            g_srcBase[n] = run;
            g_srcCur[n]  = run;
            run += cnts[q];
        }
    }
}

// ---------------- 7. scatter winners into src-sorted arrays ----------------
__global__ void scatter_kernel(const int* __restrict__ ei, const float* __restrict__ ew) {
    int e = blockIdx.x * blockDim.x + threadIdx.x;
    if (e >= E_EDGES) return;
    if (g_flags[e]) {
        int src = ei[e];
        int pos = atomicAdd(&g_srcCur[src], 1);
        g_sDst[pos] = ei[E_EDGES + e];
        g_sEw[pos]  = ew[e];
    }
}

// ---------------- 8. warp-per-src accumulate (atomic-free), direct out ----------------
__global__ __launch_bounds__(1024) void acc_kernel(float* __restrict__ out) {
    const unsigned FULL = 0xFFFFFFFFu;
    int lane = threadIdx.x & 31;
    int gw = (blockIdx.x * blockDim.x + threadIdx.x) >> 5;
    int nwarps = (gridDim.x * blockDim.x) >> 5;
    int sA = lane >> 2;            // exp source lane for channel lane
    int sB = 8 + (lane >> 2);      // exp source lane for channel lane+32

    for (int src = gw; src < N_NODES; src += nwarps) {
        int cnt  = g_srcCnt[src];
        int base = g_srcBase[src];
        float a0 = 0.f, a1 = 0.f, ds = 0.f;
        int i = 0;
        for (; i + 2 <= cnt; i += 2) {
            int   d0 = g_sDst[base + i];
            int   d1 = g_sDst[base + i + 1];
            float w0 = g_sEw[base + i];
            float w1 = g_sEw[base + i + 1];
            float ex0 = 0.f, ex1 = 0.f;
            if (lane < 16) {
                ex0 = __expf(g_beta[d0*NSTEP + lane] * w0);
                ex1 = __expf(g_beta[d1*NSTEP + lane] * w1);
            }
            float e00 = __shfl_sync(FULL, ex0, sA);
            float e01 = __shfl_sync(FULL, ex0, sB);
            float e10 = __shfl_sync(FULL, ex1, sA);
            float e11 = __shfl_sync(FULL, ex1, sB);
            float v00 = g_val[d0*64 + lane];
            float v01 = g_val[d0*64 + 32 + lane];
            float v10 = g_val[d1*64 + lane];
            float v11 = g_val[d1*64 + 32 + lane];
            a0 = fmaf(e00, v00, a0);
            a1 = fmaf(e01, v01, a1);
            a0 = fmaf(e10, v10, a0);
            a1 = fmaf(e11, v11, a1);
            ds += ex0 + ex1;
        }
        if (i < cnt) {
            int   d0 = g_sDst[base + i];
            float w0 = g_sEw[base + i];
            float ex0 = 0.f;
            if (lane < 16) ex0 = __expf(g_beta[d0*NSTEP + lane] * w0);
            float e00 = __shfl_sync(FULL, ex0, sA);
            float e01 = __shfl_sync(FULL, ex0, sB);
            a0 = fmaf(e00, g_val[d0*64 + lane], a0);
            a1 = fmaf(e01, g_val[d0*64 + 32 + lane], a1);
            ds += ex0;
        }
        float dA = __shfl_sync(FULL, ds, sA) + 1e-16f;
        float dB = __shfl_sync(FULL, ds, sB) + 1e-16f;
        out[src*64 + lane]      = a0 / dA;
        out[src*64 + 32 + lane] = a1 / dB;
    }
}

// ---------------- launch ----------------
extern "C" void kernel_launch(void* const* d_in, const int* in_sizes, int n_in,
                              void* d_out, int out_size) {
    const float* x   = (const float*)d_in[0];
    const float* p_t = (const float*)d_in[1];
    const int*   ei  = (const int*)  d_in[2];
    const float* ew  = (const float*)d_in[3];
    const float* Wv  = (const float*)d_in[4];
    const float* bv  = (const float*)d_in[5];
    const float* Wi  = (const float*)d_in[6];
    const float* bi  = (const float*)d_in[7];
    const float* mw  = (const float*)d_in[8];
    float* out = (float*)d_out;

    const int EB = (E_EDGES + 255)/256;

    prep_kernel<<<148, 256>>>(Wi, bi, p_t);
    node_kernel<<<N_NODES/NB, 256>>>(x, Wv, bv, Wi, bi, mw);
    keyhist_kernel<<<EB, 256>>>(ei, ew);
    scanB_kernel<<<1, 1024>>>();
    flagcnt_kernel<<<EB, 256>>>(ei);
    resolve_kernel<<<1, 1024>>>(ei);
    scatter_kernel<<<EB, 256>>>(ei, ew);
    acc_kernel<<<320, 1024>>>(out);
}

// round 6
// speedup vs baseline: 1.4764x; 1.2540x over previous
#include <cuda_runtime.h>

#define N_NODES 10000
#define IN_CH   128
#define OUT_CH  64
#define NSTEP   16
#define E_EDGES 320000
#define K_SEL   (E_EDGES/2)
#define NB      16
#define CAND_CAP 65536

// ---------------- device scratch ----------------
__device__ float         g_beta[N_NODES*NSTEP];
__device__ float         g_mean_beta[N_NODES];
__device__ float         g_val[N_NODES*OUT_CH];
__device__ float         g_Weff[IN_CH*16];
__device__ float         g_beff[16];
__device__ unsigned int  g_keys[E_EDGES];
__device__ unsigned char g_flags[E_EDGES];
__device__ unsigned int  g_hist16[65536];
__device__ int           g_srcCnt[N_NODES];
__device__ int           g_srcBase[N_NODES];
__device__ int           g_srcCur[N_NODES];
__device__ int           g_sDst[K_SEL];
__device__ float         g_sEw[K_SEL];
__device__ unsigned int  g_candK[CAND_CAP];
__device__ int           g_candE[CAND_CAP];
__device__ int           g_cand_cnt;
__device__ unsigned int  g_B;
__device__ int           g_R;

__device__ __forceinline__ unsigned int fxform(float f) {
    unsigned int u = __float_as_uint(f);
    return (u & 0x80000000u) ? ~u : (u | 0x80000000u);
}

// ---------------- 1. prep: zero scratch (vectorized) + Weff precontraction ----------------
__global__ void prep_kernel(const float* __restrict__ Wi,
                            const float* __restrict__ bi,
                            const float* __restrict__ p_t) {
    int t = blockIdx.x * blockDim.x + threadIdx.x;
    int stride = gridDim.x * blockDim.x;
    uint4 z4 = make_uint4(0u, 0u, 0u, 0u);
    uint4* h4 = reinterpret_cast<uint4*>(g_hist16);
    for (int i = t; i < 65536/4; i += stride) h4[i] = z4;
    int4* c4 = reinterpret_cast<int4*>(g_srcCnt);
    int4 zi4 = make_int4(0, 0, 0, 0);
    for (int i = t; i < N_NODES/4; i += stride) c4[i] = zi4;
    if (t == 0) g_cand_cnt = 0;
    if (t < IN_CH*16) {
        int c = t >> 4, s = t & 15;
        const float* w = Wi + c*512 + s*32 + 16;
        const float* p = p_t + s*16;
        float sum = 0.f;
        #pragma unroll
        for (int k = 0; k < 16; k++) sum = fmaf(w[k], p[k], sum);
        g_Weff[c*16 + s] = sum;
    }
    if (t < 16) {
        const float* b = bi + t*32 + 16;
        const float* p = p_t + t*16;
        float sum = 0.f;
        #pragma unroll
        for (int k = 0; k < 16; k++) sum = fmaf(b[k], p[k], sum);
        g_beff[t] = sum;
    }
}

// ---------------- 2. node GEMM (336 effective cols) + beta ----------------
__global__ __launch_bounds__(256) void node_kernel(
    const float* __restrict__ x,
    const float* __restrict__ Wv, const float* __restrict__ bv,
    const float* __restrict__ Wi, const float* __restrict__ bi,
    const float* __restrict__ mw)
{
    __shared__ float4 xs4[NB][32];
    __shared__ float  hwS[NB][16][17];
    __shared__ float  effS[NB][16];
    __shared__ float  betaS[NB][17];

    int tid   = threadIdx.x;
    int node0 = blockIdx.x * NB;

    for (int idx = tid; idx < NB*32; idx += 256) {
        int n = idx >> 5, k4 = idx & 31;
        xs4[n][k4] = reinterpret_cast<const float4*>(x)[(node0 + n)*32 + k4];
    }
    __syncthreads();

    const int s0 = tid >> 4, k0 = tid & 15;
    const int colA = s0*32 + k0;

    const float* pB = Wv;  int strideB = 0; bool hasB = false;
    if (tid < 64)       { pB = Wv + tid;            strideB = 64; hasB = true; }
    else if (tid < 80)  { pB = g_Weff + (tid - 64); strideB = 16; hasB = true; }

    float acc0[NB], acc1[NB];
    #pragma unroll
    for (int n = 0; n < NB; n++) { acc0[n] = 0.f; acc1[n] = 0.f; }

    for (int k4 = 0; k4 < 32; k4++) {
        int k = k4 * 4;
        float w00 = Wi[(k+0)*512 + colA];
        float w01 = Wi[(k+1)*512 + colA];
        float w02 = Wi[(k+2)*512 + colA];
        float w03 = Wi[(k+3)*512 + colA];
        float w10 = 0.f, w11 = 0.f, w12 = 0.f, w13 = 0.f;
        if (hasB) {
            w10 = pB[(k+0)*strideB]; w11 = pB[(k+1)*strideB];
            w12 = pB[(k+2)*strideB]; w13 = pB[(k+3)*strideB];
        }
        #pragma unroll
        for (int n = 0; n < NB; n++) {
            float4 xv = xs4[n][k4];
            acc0[n] = fmaf(xv.x, w00, acc0[n]);
            acc0[n] = fmaf(xv.y, w01, acc0[n]);
            acc0[n] = fmaf(xv.z, w02, acc0[n]);
            acc0[n] = fmaf(xv.w, w03, acc0[n]);
            acc1[n] = fmaf(xv.x, w10, acc1[n]);
            acc1[n] = fmaf(xv.y, w11, acc1[n]);
            acc1[n] = fmaf(xv.z, w12, acc1[n]);
            acc1[n] = fmaf(xv.w, w13, acc1[n]);
        }
    }

    {
        float b0 = bi[colA];
        #pragma unroll
        for (int n = 0; n < NB; n++) hwS[n][s0][k0] = acc0[n] + b0;
    }
    if (tid < 64) {
        float bvv = bv[tid];
        #pragma unroll
        for (int n = 0; n < NB; n++) {
            float v = acc1[n] + bvv;
            g_val[(node0 + n)*64 + tid] = v > 0.f ? v : 0.f;
        }
    } else if (tid < 80) {
        int s = tid - 64;
        #pragma unroll
        for (int n = 0; n < NB; n++) effS[n][s] = acc1[n];
    }
    __syncthreads();

    {
        int n = tid >> 4, s = tid & 15;
        const float* mwrow = mw + (node0 + n)*16;
        float sum = 0.f;
        #pragma unroll
        for (int k = 0; k < 16; k++) sum = fmaf(hwS[n][s][k], mwrow[k], sum);
        float b = (sum + effS[n][s] + g_beff[s]) * (1.0f/32.0f);
        betaS[n][s] = b;
        g_beta[(node0 + n)*NSTEP + s] = b;
    }
    __syncthreads();
    if (tid < NB) {
        float s = 0.f;
        #pragma unroll
        for (int k = 0; k < NSTEP; k++) s += betaS[tid][k];
        g_mean_beta[node0 + tid] = s * (1.0f/NSTEP);
    }
}

// ---------------- 3. keys + 16-bit histogram ----------------
__global__ void keyhist_kernel(const int* __restrict__ ei, const float* __restrict__ ew) {
    int e = blockIdx.x * blockDim.x + threadIdx.x;
    if (e >= E_EDGES) return;
    int lane = threadIdx.x & 31;
    int dst = ei[E_EDGES + e];
    float s = ew[e] * g_mean_beta[dst];
    s += 0.0f;                                 // -0 -> +0
    unsigned int k = fxform(s);
    g_keys[e] = k;
    unsigned int bin = k >> 16;
    unsigned int m = __match_any_sync(__activemask(), bin);
    int ldr = __ffs(m) - 1;
    if (lane == ldr) atomicAdd(&g_hist16[bin], __popc(m));
}

// ---------------- 4. scan: coalesced two-level threshold search ----------------
__global__ __launch_bounds__(1024) void scanB_kernel() {
    __shared__ unsigned int s_chunk[64];
    __shared__ unsigned int s_scan[1024];
    __shared__ int          s_cstar;
    __shared__ unsigned int s_cumAbove;

    int tid  = threadIdx.x;
    int w    = tid >> 5, lane = tid & 31;

    // phase 1: warp w sums chunks 2w and 2w+1 (1024 bins each), coalesced
    #pragma unroll
    for (int q = 0; q < 2; q++) {
        int c = w*2 + q;
        const unsigned int* p = &g_hist16[c*1024];
        unsigned int sum = 0;
        #pragma unroll
        for (int i = 0; i < 32; i++) sum += p[i*32 + lane];
        #pragma unroll
        for (int off = 16; off; off >>= 1) sum += __shfl_down_sync(0xFFFFFFFFu, sum, off);
        if (lane == 0) s_chunk[c] = sum;
    }
    __syncthreads();

    // phase 2: locate chunk containing the K-th element (descending)
    if (tid == 0) {
        unsigned int cum = 0;
        int cs = 0;
        for (int c = 63; c >= 0; c--) {
            unsigned int s = s_chunk[c];
            if (cum + s >= (unsigned)K_SEL) { cs = c; break; }
            cum += s;
        }
        s_cstar = cs; s_cumAbove = cum;
    }
    __syncthreads();
    int cs = s_cstar;
    unsigned int cumAbove = s_cumAbove;

    // phase 3: suffix-scan the 1024 bins of the chosen chunk
    unsigned int v = g_hist16[cs*1024 + tid];
    s_scan[tid] = v;
    __syncthreads();
    for (int off = 1; off < 1024; off <<= 1) {
        unsigned int a = (tid + off < 1024) ? s_scan[tid + off] : 0u;
        unsigned int b = s_scan[tid];
        __syncthreads();
        s_scan[tid] = b + a;
        __syncthreads();
    }
    unsigned int incl  = s_scan[tid];           // bins >= tid within chunk
    unsigned int above = cumAbove + incl - v;   // strictly above bin tid
    if (above < (unsigned)K_SEL && above + v >= (unsigned)K_SEL) {
        g_B = (unsigned)(cs*1024 + tid);
        g_R = K_SEL - (int)above;
    }
}

// ---------------- 5. flag winners + per-src counts + candidates ----------------
__global__ void flagcnt_kernel(const int* __restrict__ ei) {
    int e = blockIdx.x * blockDim.x + threadIdx.x;
    if (e >= E_EDGES) return;
    unsigned int k = g_keys[e];
    unsigned int B = g_B;
    unsigned int t16 = k >> 16;
    unsigned char f = 0;
    if (t16 > B) {
        f = 1;
        atomicAdd(&g_srcCnt[ei[e]], 1);
    } else if (t16 == B) {
        int p = atomicAdd(&g_cand_cnt, 1);
        if (p < CAND_CAP) { g_candK[p] = k; g_candE[p] = e; }
    }
    g_flags[e] = f;
}

// ---------------- 6. resolve ties + prefix-sum src counts ----------------
__global__ __launch_bounds__(1024) void resolve_kernel(const int* __restrict__ ei) {
    __shared__ unsigned int s_key[4096];
    __shared__ int          s_idx[4096];
    __shared__ unsigned int s_scan[1024];

    int C = g_cand_cnt; if (C > CAND_CAP) C = CAND_CAP;
    int R = g_R;
    if (C <= 4096) {
        for (int i = threadIdx.x; i < C; i += 1024) { s_key[i] = g_candK[i]; s_idx[i] = g_candE[i]; }
        __syncthreads();
        for (int i = threadIdx.x; i < C; i += 1024) {
            unsigned int ki = s_key[i]; int xi = s_idx[i];
            int rank = 0;
            for (int j = 0; j < C; j++) {
                unsigned int kj = s_key[j];
                rank += (kj > ki) || (kj == ki && s_idx[j] < xi);
            }
            if (rank < R) {                  // stable: smallest index wins among equals
                g_flags[xi] = 1;
                atomicAdd(&g_srcCnt[ei[xi]], 1);
            }
        }
    } else {                                  // pathological fallback
        for (int i = threadIdx.x; i < C; i += 1024) {
            unsigned int ki = g_candK[i]; int xi = g_candE[i];
            int rank = 0;
            for (int j = 0; j < C; j++) {
                unsigned int kj = g_candK[j];
                rank += (kj > ki) || (kj == ki && g_candE[j] < xi);
            }
            if (rank < R) { g_flags[xi] = 1; atomicAdd(&g_srcCnt[ei[xi]], 1); }
        }
    }
    __threadfence();
    __syncthreads();

    // exclusive prefix over g_srcCnt, 10 nodes/thread
    int nbase = threadIdx.x * 10;
    int lsum = 0;
    int cnts[10];
    #pragma unroll
    for (int q = 0; q < 10; q++) {
        int n = nbase + q;
        cnts[q] = (n < N_NODES) ? g_srcCnt[n] : 0;
        lsum += cnts[q];
    }
    s_scan[threadIdx.x] = (unsigned)lsum;
    __syncthreads();
    for (int off = 1; off < 1024; off <<= 1) {
        unsigned int a = (threadIdx.x >= off) ? s_scan[threadIdx.x - off] : 0u;
        unsigned int b = s_scan[threadIdx.x];
        __syncthreads();
        s_scan[threadIdx.x] = b + a;
        __syncthreads();
    }
    int run = (int)s_scan[threadIdx.x] - lsum;
    #pragma unroll
    for (int q = 0; q < 10; q++) {
        int n = nbase + q;
        if (n < N_NODES) {
            g_srcBase[n] = run;
            g_srcCur[n]  = run;
            run += cnts[q];
        }
    }
}

// ---------------- 7. scatter winners into src-sorted arrays ----------------
__global__ void scatter_kernel(const int* __restrict__ ei, const float* __restrict__ ew) {
    int e = blockIdx.x * blockDim.x + threadIdx.x;
    if (e >= E_EDGES) return;
    if (g_flags[e]) {
        int src = ei[e];
        int pos = atomicAdd(&g_srcCur[src], 1);
        g_sDst[pos] = ei[E_EDGES + e];
        g_sEw[pos]  = ew[e];
    }
}

// ---------------- 8. warp-per-src accumulate (atomic-free), direct out ----------------
__global__ __launch_bounds__(1024) void acc_kernel(float* __restrict__ out) {
    const unsigned FULL = 0xFFFFFFFFu;
    int lane = threadIdx.x & 31;
    int gw = (blockIdx.x * blockDim.x + threadIdx.x) >> 5;
    int nwarps = (gridDim.x * blockDim.x) >> 5;
    int sA = lane >> 2;            // exp source lane for channel lane
    int sB = 8 + (lane >> 2);      // exp source lane for channel lane+32

    for (int src = gw; src < N_NODES; src += nwarps) {
        int cnt  = g_srcCnt[src];
        int base = g_srcBase[src];
        float a0 = 0.f, a1 = 0.f, ds = 0.f;
        int i = 0;
        for (; i + 2 <= cnt; i += 2) {
            int   d0 = g_sDst[base + i];
            int   d1 = g_sDst[base + i + 1];
            float w0 = g_sEw[base + i];
            float w1 = g_sEw[base + i + 1];
            float ex0 = 0.f, ex1 = 0.f;
            if (lane < 16) {
                ex0 = __expf(g_beta[d0*NSTEP + lane] * w0);
                ex1 = __expf(g_beta[d1*NSTEP + lane] * w1);
            }
            float e00 = __shfl_sync(FULL, ex0, sA);
            float e01 = __shfl_sync(FULL, ex0, sB);
            float e10 = __shfl_sync(FULL, ex1, sA);
            float e11 = __shfl_sync(FULL, ex1, sB);
            float v00 = g_val[d0*64 + lane];
            float v01 = g_val[d0*64 + 32 + lane];
            float v10 = g_val[d1*64 + lane];
            float v11 = g_val[d1*64 + 32 + lane];
            a0 = fmaf(e00, v00, a0);
            a1 = fmaf(e01, v01, a1);
            a0 = fmaf(e10, v10, a0);
            a1 = fmaf(e11, v11, a1);
            ds += ex0 + ex1;
        }
        if (i < cnt) {
            int   d0 = g_sDst[base + i];
            float w0 = g_sEw[base + i];
            float ex0 = 0.f;
            if (lane < 16) ex0 = __expf(g_beta[d0*NSTEP + lane] * w0);
            float e00 = __shfl_sync(FULL, ex0, sA);
            float e01 = __shfl_sync(FULL, ex0, sB);
            a0 = fmaf(e00, g_val[d0*64 + lane], a0);
            a1 = fmaf(e01, g_val[d0*64 + 32 + lane], a1);
            ds += ex0;
        }
        float dA = __shfl_sync(FULL, ds, sA) + 1e-16f;
        float dB = __shfl_sync(FULL, ds, sB) + 1e-16f;
        out[src*64 + lane]      = a0 / dA;
        out[src*64 + 32 + lane] = a1 / dB;
    }
}

// ---------------- launch ----------------
extern "C" void kernel_launch(void* const* d_in, const int* in_sizes, int n_in,
                              void* d_out, int out_size) {
    const float* x   = (const float*)d_in[0];
    const float* p_t = (const float*)d_in[1];
    const int*   ei  = (const int*)  d_in[2];
    const float* ew  = (const float*)d_in[3];
    const float* Wv  = (const float*)d_in[4];
    const float* bv  = (const float*)d_in[5];
    const float* Wi  = (const float*)d_in[6];
    const float* bi  = (const float*)d_in[7];
    const float* mw  = (const float*)d_in[8];
    float* out = (float*)d_out;

    const int EB = (E_EDGES + 255)/256;

    prep_kernel<<<512, 256>>>(Wi, bi, p_t);
    node_kernel<<<N_NODES/NB, 256>>>(x, Wv, bv, Wi, bi, mw);
    keyhist_kernel<<<EB, 256>>>(ei, ew);
    scanB_kernel<<<1, 1024>>>();
    flagcnt_kernel<<<EB, 256>>>(ei);
    resolve_kernel<<<1, 1024>>>(ei);
    scatter_kernel<<<EB, 256>>>(ei, ew);
    acc_kernel<<<320, 1024>>>(out);
}

// round 8
// speedup vs baseline: 1.5503x; 1.0500x over previous
#include <cuda_runtime.h>

#define N_NODES 10000
#define IN_CH   128
#define OUT_CH  64
#define NSTEP   16
#define E_EDGES 320000
#define K_SEL   (E_EDGES/2)
#define NB      40
#define NTH     352
#define CAND_CAP 65536

// ---------------- device scratch ----------------
__device__ float         g_beta[N_NODES*NSTEP];
__device__ float         g_mean_beta[N_NODES];
__device__ float         g_val[N_NODES*OUT_CH];
__device__ float         g_Weff[IN_CH*16];
__device__ float         g_beff[16];
__device__ unsigned int  g_keys[E_EDGES];
__device__ unsigned char g_flags[E_EDGES];
__device__ unsigned int  g_hist16[65536];
__device__ unsigned int  g_chunk[64];
__device__ int           g_srcCnt[N_NODES];
__device__ int           g_srcBase[N_NODES];
__device__ int           g_srcCur[N_NODES];
__device__ int           g_sDst[K_SEL];
__device__ float         g_sEw[K_SEL];
__device__ unsigned int  g_candK[CAND_CAP];
__device__ int           g_candE[CAND_CAP];
__device__ int           g_cand_cnt;
__device__ unsigned int  g_B;
__device__ int           g_R;

__device__ __forceinline__ unsigned int fxform(float f) {
    unsigned int u = __float_as_uint(f);
    return (u & 0x80000000u) ? ~u : (u | 0x80000000u);
}

// ---------------- 1. prep ----------------
__global__ void prep_kernel(const float* __restrict__ Wi,
                            const float* __restrict__ bi,
                            const float* __restrict__ p_t) {
    int t = blockIdx.x * blockDim.x + threadIdx.x;
    int stride = gridDim.x * blockDim.x;
    uint4 z4 = make_uint4(0u, 0u, 0u, 0u);
    uint4* h4 = reinterpret_cast<uint4*>(g_hist16);
    for (int i = t; i < 65536/4; i += stride) h4[i] = z4;
    int4* c4 = reinterpret_cast<int4*>(g_srcCnt);
    int4 zi4 = make_int4(0, 0, 0, 0);
    for (int i = t; i < N_NODES/4; i += stride) c4[i] = zi4;
    if (t < 64) g_chunk[t] = 0u;
    if (t == 0) g_cand_cnt = 0;
    if (t < IN_CH*16) {
        int c = t >> 4, s = t & 15;
        const float* w = Wi + c*512 + s*32 + 16;
        const float* p = p_t + s*16;
        float sum = 0.f;
        #pragma unroll
        for (int k = 0; k < 16; k++) sum = fmaf(w[k], p[k], sum);
        g_Weff[c*16 + s] = sum;
    }
    if (t < 16) {
        const float* b = bi + t*32 + 16;
        const float* p = p_t + t*16;
        float sum = 0.f;
        #pragma unroll
        for (int k = 0; k < 16; k++) sum = fmaf(b[k], p[k], sum);
        g_beff[t] = sum;
    }
}

// ---------------- 2. node GEMM: 336 threads = 336 cols, zero waste ----------------
__global__ __launch_bounds__(NTH) void node_kernel(
    const float* __restrict__ x,
    const float* __restrict__ Wv, const float* __restrict__ bv,
    const float* __restrict__ Wi, const float* __restrict__ bi,
    const float* __restrict__ mw)
{
    __shared__ float4 xs4[NB][32];      // 20KB
    __shared__ float  mwS[NB][16];      // 2.5KB
    __shared__ float  effS[NB][16];     // 2.5KB
    __shared__ float  betaS[NB][17];    // 2.7KB

    const int tid   = threadIdx.x;
    const int node0 = blockIdx.x * NB;
    const unsigned FULL = 0xFFFFFFFFu;

    for (int idx = tid; idx < NB*32; idx += NTH) {
        int n = idx >> 5, k4 = idx & 31;
        xs4[n][k4] = reinterpret_cast<const float4*>(x)[(node0 + n)*32 + k4];
    }
    for (int idx = tid; idx < NB*16; idx += NTH) {
        int n = idx >> 4, k = idx & 15;
        mwS[n][k] = mw[(node0 + n)*16 + k];
    }
    __syncthreads();

    const bool active = (tid < 336);
    const float* wptr;
    int st;
    if (tid < 256)      { wptr = Wi + (tid >> 4)*32 + (tid & 15); st = 512; }
    else if (tid < 320) { wptr = Wv + (tid - 256);                st = 64; }
    else if (tid < 336) { wptr = g_Weff + (tid - 320);            st = 16; }
    else                { wptr = Wi;                              st = 0;  }

    float acc[NB];
    #pragma unroll
    for (int n = 0; n < NB; n++) acc[n] = 0.f;

    if (active) {
        for (int k4 = 0; k4 < 32; k4++) {
            float w0 = wptr[0];
            float w1 = wptr[st];
            float w2 = wptr[2*st];
            float w3 = wptr[3*st];
            wptr += 4*st;
            #pragma unroll
            for (int n = 0; n < NB; n++) {
                float4 xv = xs4[n][k4];
                acc[n] = fmaf(xv.x, w0, acc[n]);
                acc[n] = fmaf(xv.y, w1, acc[n]);
                acc[n] = fmaf(xv.z, w2, acc[n]);
                acc[n] = fmaf(xv.w, w3, acc[n]);
            }
        }
    }

    // epilogue part 1: Wv -> g_val (relu), Weff -> effS
    if (tid >= 256 && tid < 320) {
        int c = tid - 256;
        float bvv = bv[c];
        #pragma unroll
        for (int n = 0; n < NB; n++) {
            float v = acc[n] + bvv;
            g_val[(node0 + n)*64 + c] = v > 0.f ? v : 0.f;
        }
    } else if (tid >= 320 && tid < 336) {
        int s = tid - 320;
        #pragma unroll
        for (int n = 0; n < NB; n++) effS[n][s] = acc[n];
    }
    __syncthreads();

    // epilogue part 2: Wi threads -> beta via half-warp butterfly over k
    if (tid < 256) {
        int s0 = tid >> 4, k0 = tid & 15;
        float b0 = bi[s0*32 + k0];
        float beffv = g_beff[s0];
        #pragma unroll
        for (int n = 0; n < NB; n++) {
            float c = (acc[n] + b0) * mwS[n][k0];
            c += __shfl_xor_sync(FULL, c, 1);
            c += __shfl_xor_sync(FULL, c, 2);
            c += __shfl_xor_sync(FULL, c, 4);
            c += __shfl_xor_sync(FULL, c, 8);
            if (k0 == 0)
                betaS[n][s0] = (c + effS[n][s0] + beffv) * (1.0f/32.0f);
        }
    }
    __syncthreads();

    // coalesced beta store + mean
    for (int idx = tid; idx < NB*16; idx += NTH) {
        int n = idx >> 4, s = idx & 15;
        g_beta[(node0 + n)*NSTEP + s] = betaS[n][s];
    }
    if (tid < NB) {
        float s = 0.f;
        #pragma unroll
        for (int k = 0; k < NSTEP; k++) s += betaS[tid][k];
        g_mean_beta[node0 + tid] = s * (1.0f/NSTEP);
    }
}

// ---------------- 3. keys + 16-bit histogram + chunk sums ----------------
__global__ void keyhist_kernel(const int* __restrict__ ei, const float* __restrict__ ew) {
    int e = blockIdx.x * blockDim.x + threadIdx.x;
    if (e >= E_EDGES) return;
    int lane = threadIdx.x & 31;
    int dst = ei[E_EDGES + e];
    float s = ew[e] * g_mean_beta[dst];
    s += 0.0f;                                 // -0 -> +0
    unsigned int k = fxform(s);
    g_keys[e] = k;
    unsigned int bin = k >> 16;
    unsigned int am = __activemask();
    unsigned int m = __match_any_sync(am, bin);
    if (lane == __ffs(m) - 1) atomicAdd(&g_hist16[bin], __popc(m));
    unsigned int ch = bin >> 10;
    unsigned int m2 = __match_any_sync(am, ch);
    if (lane == __ffs(m2) - 1) atomicAdd(&g_chunk[ch], __popc(m2));
}

// ---------------- 4. scan: chunk walk + one-chunk suffix scan ----------------
__global__ __launch_bounds__(1024) void scanB_kernel() {
    __shared__ unsigned int s_chunk[64];
    __shared__ unsigned int s_scan[1024];
    __shared__ int          s_cstar;
    __shared__ unsigned int s_cumAbove;

    int tid = threadIdx.x;
    if (tid < 64) s_chunk[tid] = g_chunk[tid];
    __syncthreads();
    if (tid == 0) {
        unsigned int cum = 0;
        int cs = 0;
        for (int c = 63; c >= 0; c--) {
            unsigned int s = s_chunk[c];
            if (cum + s >= (unsigned)K_SEL) { cs = c; break; }
            cum += s;
        }
        s_cstar = cs; s_cumAbove = cum;
    }
    __syncthreads();
    int cs = s_cstar;
    unsigned int cumAbove = s_cumAbove;

    unsigned int v = g_hist16[cs*1024 + tid];
    s_scan[tid] = v;
    __syncthreads();
    for (int off = 1; off < 1024; off <<= 1) {
        unsigned int a = (tid + off < 1024) ? s_scan[tid + off] : 0u;
        unsigned int b = s_scan[tid];
        __syncthreads();
        s_scan[tid] = b + a;
        __syncthreads();
    }
    unsigned int incl  = s_scan[tid];
    unsigned int above = cumAbove + incl - v;
    if (above < (unsigned)K_SEL && above + v >= (unsigned)K_SEL) {
        g_B = (unsigned)(cs*1024 + tid);
        g_R = K_SEL - (int)above;
    }
}

// ---------------- 5. flag winners + per-src counts + candidates ----------------
__global__ void flagcnt_kernel(const int* __restrict__ ei) {
    int e = blockIdx.x * blockDim.x + threadIdx.x;
    if (e >= E_EDGES) return;
    unsigned int k = g_keys[e];
    unsigned int B = g_B;
    unsigned int t16 = k >> 16;
    unsigned char f = 0;
    if (t16 > B) {
        f = 1;
        atomicAdd(&g_srcCnt[ei[e]], 1);
    } else if (t16 == B) {
        int p = atomicAdd(&g_cand_cnt, 1);
        if (p < CAND_CAP) { g_candK[p] = k; g_candE[p] = e; }
    }
    g_flags[e] = f;
}

// ---------------- 6. resolve ties + prefix-sum src counts ----------------
__global__ __launch_bounds__(1024) void resolve_kernel(const int* __restrict__ ei) {
    __shared__ unsigned int s_key[4096];
    __shared__ int          s_idx[4096];
    __shared__ unsigned int s_scan[1024];

    int C = g_cand_cnt; if (C > CAND_CAP) C = CAND_CAP;
    int R = g_R;
    if (C <= 4096) {
        for (int i = threadIdx.x; i < C; i += 1024) { s_key[i] = g_candK[i]; s_idx[i] = g_candE[i]; }
        __syncthreads();
        for (int i = threadIdx.x; i < C; i += 1024) {
            unsigned int ki = s_key[i]; int xi = s_idx[i];
            int rank = 0;
            for (int j = 0; j < C; j++) {
                unsigned int kj = s_key[j];
                rank += (kj > ki) || (kj == ki && s_idx[j] < xi);
            }
            if (rank < R) {
                g_flags[xi] = 1;
                atomicAdd(&g_srcCnt[ei[xi]], 1);
            }
        }
    } else {
        for (int i = threadIdx.x; i < C; i += 1024) {
            unsigned int ki = g_candK[i]; int xi = g_candE[i];
            int rank = 0;
            for (int j = 0; j < C; j++) {
                unsigned int kj = g_candK[j];
                rank += (kj > ki) || (kj == ki && g_candE[j] < xi);
            }
            if (rank < R) { g_flags[xi] = 1; atomicAdd(&g_srcCnt[ei[xi]], 1); }
        }
    }
    __threadfence();
    __syncthreads();

    int nbase = threadIdx.x * 10;
    int lsum = 0;
    int cnts[10];
    #pragma unroll
    for (int q = 0; q < 10; q++) {
        int n = nbase + q;
        cnts[q] = (n < N_NODES) ? g_srcCnt[n] : 0;
        lsum += cnts[q];
    }
    s_scan[threadIdx.x] = (unsigned)lsum;
    __syncthreads();
    for (int off = 1; off < 1024; off <<= 1) {
        unsigned int a = (threadIdx.x >= off) ? s_scan[threadIdx.x - off] : 0u;
        unsigned int b = s_scan[threadIdx.x];
        __syncthreads();
        s_scan[threadIdx.x] = b + a;
        __syncthreads();
    }
    int run = (int)s_scan[threadIdx.x] - lsum;
    #pragma unroll
    for (int q = 0; q < 10; q++) {
        int n = nbase + q;
        if (n < N_NODES) {
            g_srcBase[n] = run;
            g_srcCur[n]  = run;
            run += cnts[q];
        }
    }
}

// ---------------- 7. scatter ----------------
__global__ void scatter_kernel(const int* __restrict__ ei, const float* __restrict__ ew) {
    int e = blockIdx.x * blockDim.x + threadIdx.x;
    if (e >= E_EDGES) return;
    if (g_flags[e]) {
        int src = ei[e];
        int pos = atomicAdd(&g_srcCur[src], 1);
        g_sDst[pos] = ei[E_EDGES + e];
        g_sEw[pos]  = ew[e];
    }
}

// ---------------- 8. warp-per-src accumulate ----------------
__global__ __launch_bounds__(1024) void acc_kernel(float* __restrict__ out) {
    const unsigned FULL = 0xFFFFFFFFu;
    int lane = threadIdx.x & 31;
    int gw = (blockIdx.x * blockDim.x + threadIdx.x) >> 5;
    int nwarps = (gridDim.x * blockDim.x) >> 5;
    int sA = lane >> 2;
    int sB = 8 + (lane >> 2);

    for (int src = gw; src < N_NODES; src += nwarps) {
        int cnt  = g_srcCnt[src];
        int base = g_srcBase[src];
        float a0 = 0.f, a1 = 0.f, ds = 0.f;
        int i = 0;
        for (; i + 2 <= cnt; i += 2) {
            int   d0 = g_sDst[base + i];
            int   d1 = g_sDst[base + i + 1];
            float w0 = g_sEw[base + i];
            float w1 = g_sEw[base + i + 1];
            float ex0 = 0.f, ex1 = 0.f;
            if (lane < 16) {
                ex0 = __expf(g_beta[d0*NSTEP + lane] * w0);
                ex1 = __expf(g_beta[d1*NSTEP + lane] * w1);
            }
            float e00 = __shfl_sync(FULL, ex0, sA);
            float e01 = __shfl_sync(FULL, ex0, sB);
            float e10 = __shfl_sync(FULL, ex1, sA);
            float e11 = __shfl_sync(FULL, ex1, sB);
            float v00 = g_val[d0*64 + lane];
            float v01 = g_val[d0*64 + 32 + lane];
            float v10 = g_val[d1*64 + lane];
            float v11 = g_val[d1*64 + 32 + lane];
            a0 = fmaf(e00, v00, a0);
            a1 = fmaf(e01, v01, a1);
            a0 = fmaf(e10, v10, a0);
            a1 = fmaf(e11, v11, a1);
            ds += ex0 + ex1;
        }
        if (i < cnt) {
            int   d0 = g_sDst[base + i];
            float w0 = g_sEw[base + i];
            float ex0 = 0.f;
            if (lane < 16) ex0 = __expf(g_beta[d0*NSTEP + lane] * w0);
            float e00 = __shfl_sync(FULL, ex0, sA);
            float e01 = __shfl_sync(FULL, ex0, sB);
            a0 = fmaf(e00, g_val[d0*64 + lane], a0);
            a1 = fmaf(e01, g_val[d0*64 + 32 + lane], a1);
            ds += ex0;
        }
        float dA = __shfl_sync(FULL, ds, sA) + 1e-16f;
        float dB = __shfl_sync(FULL, ds, sB) + 1e-16f;
        out[src*64 + lane]      = a0 / dA;
        out[src*64 + 32 + lane] = a1 / dB;
    }
}

// ---------------- launch ----------------
extern "C" void kernel_launch(void* const* d_in, const int* in_sizes, int n_in,
                              void* d_out, int out_size) {
    const float* x   = (const float*)d_in[0];
    const float* p_t = (const float*)d_in[1];
    const int*   ei  = (const int*)  d_in[2];
    const float* ew  = (const float*)d_in[3];
    const float* Wv  = (const float*)d_in[4];
    const float* bv  = (const float*)d_in[5];
    const float* Wi  = (const float*)d_in[6];
    const float* bi  = (const float*)d_in[7];
    const float* mw  = (const float*)d_in[8];
    float* out = (float*)d_out;

    const int EB = (E_EDGES + 255)/256;

    prep_kernel<<<512, 256>>>(Wi, bi, p_t);
    node_kernel<<<N_NODES/NB, NTH>>>(x, Wv, bv, Wi, bi, mw);
    keyhist_kernel<<<EB, 256>>>(ei, ew);
    scanB_kernel<<<1, 1024>>>();
    flagcnt_kernel<<<EB, 256>>>(ei);
    resolve_kernel<<<1, 1024>>>(ei);
    scatter_kernel<<<EB, 256>>>(ei, ew);
    acc_kernel<<<320, 1024>>>(out);
}

// round 9
// speedup vs baseline: 1.6605x; 1.0711x over previous
#include <cuda_runtime.h>

#define N_NODES 10000
#define IN_CH   128
#define OUT_CH  64
#define NSTEP   16
#define E_EDGES 320000
#define K_SEL   (E_EDGES/2)
#define NB      40
#define NTH     192
#define CAND_CAP 65536

// ---------------- device scratch ----------------
__device__ float         g_beta[N_NODES*NSTEP];
__device__ float         g_mean_beta[N_NODES];
__device__ float         g_val[N_NODES*OUT_CH];
__device__ float         g_Weff[IN_CH*16];
__device__ float         g_beff[16];
__device__ unsigned int  g_keys[E_EDGES];
__device__ unsigned char g_flags[E_EDGES];
__device__ unsigned int  g_hist16[65536];
__device__ unsigned int  g_chunk[64];
__device__ int           g_srcCnt[N_NODES];
__device__ int           g_srcBase[N_NODES];
__device__ int           g_srcCur[N_NODES];
__device__ int           g_sDst[K_SEL];
__device__ float         g_sEw[K_SEL];
__device__ unsigned int  g_candK[CAND_CAP];
__device__ int           g_candE[CAND_CAP];
__device__ int           g_cand_cnt;
__device__ unsigned int  g_B;
__device__ int           g_R;

__device__ __forceinline__ unsigned int fxform(float f) {
    unsigned int u = __float_as_uint(f);
    return (u & 0x80000000u) ? ~u : (u | 0x80000000u);
}

// ---------------- 1. prep ----------------
__global__ void prep_kernel(const float* __restrict__ Wi,
                            const float* __restrict__ bi,
                            const float* __restrict__ p_t) {
    int t = blockIdx.x * blockDim.x + threadIdx.x;
    int stride = gridDim.x * blockDim.x;
    uint4 z4 = make_uint4(0u, 0u, 0u, 0u);
    uint4* h4 = reinterpret_cast<uint4*>(g_hist16);
    for (int i = t; i < 65536/4; i += stride) h4[i] = z4;
    int4* c4 = reinterpret_cast<int4*>(g_srcCnt);
    int4 zi4 = make_int4(0, 0, 0, 0);
    for (int i = t; i < N_NODES/4; i += stride) c4[i] = zi4;
    if (t < 64) g_chunk[t] = 0u;
    if (t == 0) g_cand_cnt = 0;
    if (t < IN_CH*16) {
        int c = t >> 4, s = t & 15;
        const float* w = Wi + c*512 + s*32 + 16;
        const float* p = p_t + s*16;
        float sum = 0.f;
        #pragma unroll
        for (int k = 0; k < 16; k++) sum = fmaf(w[k], p[k], sum);
        g_Weff[c*16 + s] = sum;
    }
    if (t < 16) {
        const float* b = bi + t*32 + 16;
        const float* p = p_t + t*16;
        float sum = 0.f;
        #pragma unroll
        for (int k = 0; k < 16; k++) sum = fmaf(b[k], p[k], sum);
        g_beff[t] = sum;
    }
}

// ---------------- 2. node GEMM: 168 workers x 2 cols, 8 FMA per LDS ----------------
__global__ __launch_bounds__(NTH) void node_kernel(
    const float* __restrict__ x,
    const float* __restrict__ Wv, const float* __restrict__ bv,
    const float* __restrict__ Wi, const float* __restrict__ bi,
    const float* __restrict__ mw)
{
    __shared__ float4 xs4[NB][32];      // 20KB
    __shared__ float  mwS[NB][16];
    __shared__ float  effS[NB][16];
    __shared__ float  betaS[NB][17];

    const int tid   = threadIdx.x;
    const int node0 = blockIdx.x * NB;   // grid 250 * NB 40 = 10000 exact
    const unsigned FULL = 0xFFFFFFFFu;

    for (int idx = tid; idx < NB*32; idx += NTH) {
        int n = idx >> 5, k4 = idx & 31;
        xs4[n][k4] = reinterpret_cast<const float4*>(x)[(node0 + n)*32 + k4];
    }
    for (int idx = tid; idx < NB*16; idx += NTH) {
        int n = idx >> 4, k = idx & 15;
        mwS[n][k] = mw[(node0 + n)*16 + k];
    }
    __syncthreads();

    // thread tid<168 owns columns c0=2*tid, c1=2*tid+1 of the 336 effective cols
    const bool active = (tid < 168);
    const float *p0, *p1;
    int st0, st1;
    {
        int c0 = 2*tid, c1 = 2*tid + 1;
        if (c0 < 256)      { p0 = Wi + (c0 >> 4)*32 + (c0 & 15); st0 = 512; }
        else if (c0 < 320) { p0 = Wv + (c0 - 256);               st0 = 64; }
        else if (c0 < 336) { p0 = g_Weff + (c0 - 320);           st0 = 16; }
        else               { p0 = Wi;                            st0 = 0;  }
        if (c1 < 256)      { p1 = Wi + (c1 >> 4)*32 + (c1 & 15); st1 = 512; }
        else if (c1 < 320) { p1 = Wv + (c1 - 256);               st1 = 64; }
        else if (c1 < 336) { p1 = g_Weff + (c1 - 320);           st1 = 16; }
        else               { p1 = Wi;                            st1 = 0;  }
    }

    float acc0[NB], acc1[NB];
    #pragma unroll
    for (int n = 0; n < NB; n++) { acc0[n] = 0.f; acc1[n] = 0.f; }

    if (active) {
        for (int k4 = 0; k4 < 32; k4++) {
            float w00 = p0[0], w01 = p0[st0], w02 = p0[2*st0], w03 = p0[3*st0];
            float w10 = p1[0], w11 = p1[st1], w12 = p1[2*st1], w13 = p1[3*st1];
            p0 += 4*st0; p1 += 4*st1;
            #pragma unroll
            for (int n = 0; n < NB; n++) {
                float4 xv = xs4[n][k4];
                acc0[n] = fmaf(xv.x, w00, acc0[n]);
                acc0[n] = fmaf(xv.y, w01, acc0[n]);
                acc0[n] = fmaf(xv.z, w02, acc0[n]);
                acc0[n] = fmaf(xv.w, w03, acc0[n]);
                acc1[n] = fmaf(xv.x, w10, acc1[n]);
                acc1[n] = fmaf(xv.y, w11, acc1[n]);
                acc1[n] = fmaf(xv.z, w12, acc1[n]);
                acc1[n] = fmaf(xv.w, w13, acc1[n]);
            }
        }
    }

    // epilogue part 1: Wv threads -> g_val (relu, coalesced float2); Weff -> effS
    if (tid >= 128 && tid < 160) {
        int vc = tid - 128;                    // float2 column index 0..31
        float b0v = bv[2*vc], b1v = bv[2*vc + 1];
        #pragma unroll
        for (int n = 0; n < NB; n++) {
            float v0 = acc0[n] + b0v;
            float v1 = acc1[n] + b1v;
            reinterpret_cast<float2*>(g_val)[(node0 + n)*32 + vc] =
                make_float2(v0 > 0.f ? v0 : 0.f, v1 > 0.f ? v1 : 0.f);
        }
    } else if (tid >= 160 && tid < 168) {
        int s0 = 2*(tid - 160), s1 = s0 + 1;
        #pragma unroll
        for (int n = 0; n < NB; n++) { effS[n][s0] = acc0[n]; effS[n][s1] = acc1[n]; }
    }
    __syncthreads();

    // epilogue part 2: Wi threads -> beta via 8-lane butterfly (3 stages)
    if (tid < 128) {
        int s  = tid >> 3;
        int kp = (tid & 7)*2;
        float b0 = bi[s*32 + kp], b1 = bi[s*32 + kp + 1];
        float beffv = g_beff[s];
        #pragma unroll
        for (int n = 0; n < NB; n++) {
            float c = (acc0[n] + b0)*mwS[n][kp] + (acc1[n] + b1)*mwS[n][kp + 1];
            c += __shfl_xor_sync(FULL, c, 1);
            c += __shfl_xor_sync(FULL, c, 2);
            c += __shfl_xor_sync(FULL, c, 4);
            if ((tid & 7) == 0)
                betaS[n][s] = (c + effS[n][s] + beffv) * (1.0f/32.0f);
        }
    }
    __syncthreads();

    for (int idx = tid; idx < NB*16; idx += NTH) {
        int n = idx >> 4, s = idx & 15;
        g_beta[(node0 + n)*NSTEP + s] = betaS[n][s];
    }
    if (tid < NB) {
        float s = 0.f;
        #pragma unroll
        for (int k = 0; k < NSTEP; k++) s += betaS[tid][k];
        g_mean_beta[node0 + tid] = s * (1.0f/NSTEP);
    }
}

// ---------------- 3. keys + 16-bit histogram + chunk sums ----------------
__global__ void keyhist_kernel(const int* __restrict__ ei, const float* __restrict__ ew) {
    int e = blockIdx.x * blockDim.x + threadIdx.x;
    if (e >= E_EDGES) return;
    int lane = threadIdx.x & 31;
    int dst = ei[E_EDGES + e];
    float s = ew[e] * g_mean_beta[dst];
    s += 0.0f;                                 // -0 -> +0
    unsigned int k = fxform(s);
    g_keys[e] = k;
    unsigned int bin = k >> 16;
    unsigned int am = __activemask();
    unsigned int m = __match_any_sync(am, bin);
    if (lane == __ffs(m) - 1) atomicAdd(&g_hist16[bin], __popc(m));
    unsigned int ch = bin >> 10;
    unsigned int m2 = __match_any_sync(am, ch);
    if (lane == __ffs(m2) - 1) atomicAdd(&g_chunk[ch], __popc(m2));
}

// ---------------- 4. scan: chunk walk + warp-level suffix scan ----------------
__global__ __launch_bounds__(1024) void scanB_kernel() {
    __shared__ unsigned int s_chunk[64];
    __shared__ unsigned int s_wsum[32];
    __shared__ int          s_cstar;
    __shared__ unsigned int s_cumAbove;

    int tid = threadIdx.x, lane = tid & 31, w = tid >> 5;
    if (tid < 64) s_chunk[tid] = g_chunk[tid];
    __syncthreads();
    if (tid == 0) {
        unsigned int cum = 0; int cs = 0;
        for (int c = 63; c >= 0; c--) {
            unsigned int s = s_chunk[c];
            if (cum + s >= (unsigned)K_SEL) { cs = c; break; }
            cum += s;
        }
        s_cstar = cs; s_cumAbove = cum;
    }
    __syncthreads();
    int cs = s_cstar;
    unsigned int cumAbove = s_cumAbove;

    unsigned int v = g_hist16[cs*1024 + tid];
    unsigned int suf = v;
    #pragma unroll
    for (int off = 1; off < 32; off <<= 1) {
        unsigned int t2 = __shfl_down_sync(0xFFFFFFFFu, suf, off);
        if (lane + off < 32) suf += t2;
    }
    if (lane == 0) s_wsum[w] = suf;
    __syncthreads();
    if (w == 0) {
        unsigned int wv = s_wsum[lane];
        unsigned int ws = wv;
        #pragma unroll
        for (int off = 1; off < 32; off <<= 1) {
            unsigned int t2 = __shfl_down_sync(0xFFFFFFFFu, ws, off);
            if (lane + off < 32) ws += t2;
        }
        s_wsum[lane] = ws - wv;    // sum of warps strictly after lane
    }
    __syncthreads();
    unsigned int incl  = suf + s_wsum[w];     // bins >= tid within chunk
    unsigned int above = cumAbove + incl - v;
    if (above < (unsigned)K_SEL && above + v >= (unsigned)K_SEL) {
        g_B = (unsigned)(cs*1024 + tid);
        g_R = K_SEL - (int)above;
    }
}

// ---------------- 5. flag winners + per-src counts + candidates ----------------
__global__ void flagcnt_kernel(const int* __restrict__ ei) {
    int e = blockIdx.x * blockDim.x + threadIdx.x;
    if (e >= E_EDGES) return;
    unsigned int k = g_keys[e];
    unsigned int B = g_B;
    unsigned int t16 = k >> 16;
    unsigned char f = 0;
    if (t16 > B) {
        f = 1;
        atomicAdd(&g_srcCnt[ei[e]], 1);
    } else if (t16 == B) {
        int p = atomicAdd(&g_cand_cnt, 1);
        if (p < CAND_CAP) { g_candK[p] = k; g_candE[p] = e; }
    }
    g_flags[e] = f;
}

// ---------------- 6. resolve ties + prefix-sum src counts ----------------
__global__ __launch_bounds__(1024) void resolve_kernel(const int* __restrict__ ei) {
    __shared__ unsigned int s_key[4096];
    __shared__ int          s_idx[4096];
    __shared__ unsigned int s_scan[1024];

    int C = g_cand_cnt; if (C > CAND_CAP) C = CAND_CAP;
    int R = g_R;
    if (C <= 4096) {
        for (int i = threadIdx.x; i < C; i += 1024) { s_key[i] = g_candK[i]; s_idx[i] = g_candE[i]; }
        __syncthreads();
        for (int i = threadIdx.x; i < C; i += 1024) {
            unsigned int ki = s_key[i]; int xi = s_idx[i];
            int rank = 0;
            for (int j = 0; j < C; j++) {
                unsigned int kj = s_key[j];
                rank += (kj > ki) || (kj == ki && s_idx[j] < xi);
            }
            if (rank < R) {
                g_flags[xi] = 1;
                atomicAdd(&g_srcCnt[ei[xi]], 1);
            }
        }
    } else {
        for (int i = threadIdx.x; i < C; i += 1024) {
            unsigned int ki = g_candK[i]; int xi = g_candE[i];
            int rank = 0;
            for (int j = 0; j < C; j++) {
                unsigned int kj = g_candK[j];
                rank += (kj > ki) || (kj == ki && g_candE[j] < xi);
            }
            if (rank < R) { g_flags[xi] = 1; atomicAdd(&g_srcCnt[ei[xi]], 1); }
        }
    }
    __threadfence();
    __syncthreads();

    int nbase = threadIdx.x * 10;
    int lsum = 0;
    int cnts[10];
    #pragma unroll
    for (int q = 0; q < 10; q++) {
        int n = nbase + q;
        cnts[q] = (n < N_NODES) ? g_srcCnt[n] : 0;
        lsum += cnts[q];
    }
    s_scan[threadIdx.x] = (unsigned)lsum;
    __syncthreads();
    for (int off = 1; off < 1024; off <<= 1) {
        unsigned int a = (threadIdx.x >= off) ? s_scan[threadIdx.x - off] : 0u;
        unsigned int b = s_scan[threadIdx.x];
        __syncthreads();
        s_scan[threadIdx.x] = b + a;
        __syncthreads();
    }
    int run = (int)s_scan[threadIdx.x] - lsum;
    #pragma unroll
    for (int q = 0; q < 10; q++) {
        int n = nbase + q;
        if (n < N_NODES) {
            g_srcBase[n] = run;
            g_srcCur[n]  = run;
            run += cnts[q];
        }
    }
}

// ---------------- 7. scatter ----------------
__global__ void scatter_kernel(const int* __restrict__ ei, const float* __restrict__ ew) {
    int e = blockIdx.x * blockDim.x + threadIdx.x;
    if (e >= E_EDGES) return;
    if (g_flags[e]) {
        int src = ei[e];
        int pos = atomicAdd(&g_srcCur[src], 1);
        g_sDst[pos] = ei[E_EDGES + e];
        g_sEw[pos]  = ew[e];
    }
}

// ---------------- 8. warp-per-src accumulate, packed exp (full-warp MUFU) ----------------
__global__ __launch_bounds__(1024) void acc_kernel(float* __restrict__ out) {
    const unsigned FULL = 0xFFFFFFFFu;
    int lane = threadIdx.x & 31;
    int gw = (blockIdx.x * blockDim.x + threadIdx.x) >> 5;
    int nwarps = (gridDim.x * blockDim.x) >> 5;
    int sA = lane >> 2;
    int sB = 8 + (lane >> 2);

    for (int src = gw; src < N_NODES; src += nwarps) {
        int cnt  = g_srcCnt[src];
        int base = g_srcBase[src];
        float a0 = 0.f, a1 = 0.f, ds = 0.f;
        int i = 0;
        for (; i + 2 <= cnt; i += 2) {
            int   d0 = g_sDst[base + i];
            int   d1 = g_sDst[base + i + 1];
            float w0 = g_sEw[base + i];
            float w1 = g_sEw[base + i + 1];
            // lanes 0-15: edge0 steps; lanes 16-31: edge1 steps -> one full-warp MUFU
            float bval = (lane < 16) ? g_beta[d0*NSTEP + lane] * w0
                                     : g_beta[d1*NSTEP + (lane - 16)] * w1;
            float ex = __expf(bval);
            float e00 = __shfl_sync(FULL, ex, sA);
            float e01 = __shfl_sync(FULL, ex, sB);
            float e10 = __shfl_sync(FULL, ex, 16 + sA);
            float e11 = __shfl_sync(FULL, ex, 16 + sB);
            a0 = fmaf(e00, g_val[d0*64 + lane],      a0);
            a1 = fmaf(e01, g_val[d0*64 + 32 + lane], a1);
            a0 = fmaf(e10, g_val[d1*64 + lane],      a0);
            a1 = fmaf(e11, g_val[d1*64 + 32 + lane], a1);
            ds += ex;
        }
        if (i < cnt) {
            int   d0 = g_sDst[base + i];
            float w0 = g_sEw[base + i];
            float ex0 = 0.f;
            if (lane < 16) ex0 = __expf(g_beta[d0*NSTEP + lane] * w0);
            float e00 = __shfl_sync(FULL, ex0, sA);
            float e01 = __shfl_sync(FULL, ex0, sB);
            a0 = fmaf(e00, g_val[d0*64 + lane],      a0);
            a1 = fmaf(e01, g_val[d0*64 + 32 + lane], a1);
            ds += ex0;
        }
        // denom per step s = lower-half ds[s] + upper-half ds[s+16]
        float dA = __shfl_sync(FULL, ds, sA) + __shfl_sync(FULL, ds, 16 + sA) + 1e-16f;
        float dB = __shfl_sync(FULL, ds, sB) + __shfl_sync(FULL, ds, 16 + sB) + 1e-16f;
        out[src*64 + lane]      = a0 / dA;
        out[src*64 + 32 + lane] = a1 / dB;
    }
}

// ---------------- launch ----------------
extern "C" void kernel_launch(void* const* d_in, const int* in_sizes, int n_in,
                              void* d_out, int out_size) {
    const float* x   = (const float*)d_in[0];
    const float* p_t = (const float*)d_in[1];
    const int*   ei  = (const int*)  d_in[2];
    const float* ew  = (const float*)d_in[3];
    const float* Wv  = (const float*)d_in[4];
    const float* bv  = (const float*)d_in[5];
    const float* Wi  = (const float*)d_in[6];
    const float* bi  = (const float*)d_in[7];
    const float* mw  = (const float*)d_in[8];
    float* out = (float*)d_out;

    const int EB = (E_EDGES + 255)/256;

    prep_kernel<<<512, 256>>>(Wi, bi, p_t);
    node_kernel<<<N_NODES/NB, NTH>>>(x, Wv, bv, Wi, bi, mw);
    keyhist_kernel<<<EB, 256>>>(ei, ew);
    scanB_kernel<<<1, 1024>>>();
    flagcnt_kernel<<<EB, 256>>>(ei);
    resolve_kernel<<<1, 1024>>>(ei);
    scatter_kernel<<<EB, 256>>>(ei, ew);
    acc_kernel<<<320, 1024>>>(out);
}

// round 10
// speedup vs baseline: 1.6912x; 1.0185x over previous
#include <cuda_runtime.h>

#define N_NODES 10000
#define IN_CH   128
#define OUT_CH  64
#define NSTEP   16
#define E_EDGES 320000
#define K_SEL   (E_EDGES/2)
#define NB      40
#define NP      20          // node pairs per block
#define NTH     192
#define CAND_CAP 65536

// ---------------- device scratch ----------------
__device__ float         g_beta[N_NODES*NSTEP];
__device__ float         g_mean_beta[N_NODES];
__device__ float         g_val[N_NODES*OUT_CH];
__device__ float         g_Weff[IN_CH*16];
__device__ float         g_beff[16];
__device__ unsigned int  g_keys[E_EDGES];
__device__ unsigned char g_flags[E_EDGES];
__device__ unsigned int  g_hist16[65536];
__device__ unsigned int  g_chunk[64];
__device__ int           g_srcCnt[N_NODES];
__device__ int           g_srcBase[N_NODES];
__device__ int           g_srcCur[N_NODES];
__device__ int           g_sDst[K_SEL];
__device__ float         g_sEw[K_SEL];
__device__ unsigned int  g_candK[CAND_CAP];
__device__ int           g_candE[CAND_CAP];
__device__ int           g_cand_cnt;
__device__ unsigned int  g_B;
__device__ int           g_R;

__device__ __forceinline__ unsigned int fxform(float f) {
    unsigned int u = __float_as_uint(f);
    return (u & 0x80000000u) ? ~u : (u | 0x80000000u);
}

// ---- packed fp32x2 helpers ----
__device__ __forceinline__ void fma2(unsigned long long& d,
                                     unsigned long long a, unsigned long long b) {
    asm("fma.rn.f32x2 %0, %1, %2, %0;" : "+l"(d) : "l"(a), "l"(b));
}
__device__ __forceinline__ unsigned long long pack2(float v) {
    unsigned long long r;
    asm("mov.b64 %0, {%1, %1};" : "=l"(r) : "f"(v));
    return r;
}
__device__ __forceinline__ float2 unpack2(unsigned long long v) {
    float2 f;
    asm("mov.b64 {%0, %1}, %2;" : "=f"(f.x), "=f"(f.y) : "l"(v));
    return f;
}

// ---------------- 1. weff: precontract Wi upper halves with p_t ----------------
__global__ void weff_kernel(const float* __restrict__ Wi,
                            const float* __restrict__ bi,
                            const float* __restrict__ p_t) {
    int t = blockIdx.x * blockDim.x + threadIdx.x;
    if (t < IN_CH*16) {
        int c = t >> 4, s = t & 15;
        const float* w = Wi + c*512 + s*32 + 16;
        const float* p = p_t + s*16;
        float sum = 0.f;
        #pragma unroll
        for (int k = 0; k < 16; k++) sum = fmaf(w[k], p[k], sum);
        g_Weff[c*16 + s] = sum;
    }
    if (t < 16) {
        const float* b = bi + t*32 + 16;
        const float* p = p_t + t*16;
        float sum = 0.f;
        #pragma unroll
        for (int k = 0; k < 16; k++) sum = fmaf(b[k], p[k], sum);
        g_beff[t] = sum;
    }
}

// ---------------- 2. node GEMM: packed f32x2 over node pairs ----------------
__global__ __launch_bounds__(NTH) void node_kernel(
    const float* __restrict__ x,
    const float* __restrict__ Wv, const float* __restrict__ bv,
    const float* __restrict__ Wi, const float* __restrict__ bi,
    const float* __restrict__ mw)
{
    // xsQ[j][k2]: .x = packed (x[2j][2k2],   x[2j+1][2k2])
    //             .y = packed (x[2j][2k2+1], x[2j+1][2k2+1])
    __shared__ ulonglong2 xsQ[NP][64];   // 20KB
    __shared__ float      mwS[NB][16];
    __shared__ float      effS[NB][16];
    __shared__ float      betaS[NB][17];

    const int tid   = threadIdx.x;
    const int node0 = blockIdx.x * NB;   // grid 250 * 40 = 10000 exact
    const unsigned FULL = 0xFFFFFFFFu;

    {
        float* xf = reinterpret_cast<float*>(xsQ);
        for (int idx = tid; idx < NB*64; idx += NTH) {
            int n = idx >> 6, k2 = idx & 63;
            float2 v = reinterpret_cast<const float2*>(x)[(node0 + n)*64 + k2];
            int base = (n >> 1)*256 + k2*4 + (n & 1);
            xf[base]     = v.x;      // k = 2*k2
            xf[base + 2] = v.y;      // k = 2*k2+1
        }
    }
    for (int idx = tid; idx < NB*16; idx += NTH) {
        int n = idx >> 4, k = idx & 15;
        mwS[n][k] = mw[(node0 + n)*16 + k];
    }
    __syncthreads();

    // thread tid<168 owns effective columns c0=2*tid, c1=2*tid+1 (of 336)
    const bool active = (tid < 168);
    const float *p0, *p1;
    int st0, st1;
    {
        int c0 = 2*tid, c1 = 2*tid + 1;
        if (c0 < 256)      { p0 = Wi + (c0 >> 4)*32 + (c0 & 15); st0 = 512; }
        else if (c0 < 320) { p0 = Wv + (c0 - 256);               st0 = 64; }
        else if (c0 < 336) { p0 = g_Weff + (c0 - 320);           st0 = 16; }
        else               { p0 = Wi;                            st0 = 0;  }
        if (c1 < 256)      { p1 = Wi + (c1 >> 4)*32 + (c1 & 15); st1 = 512; }
        else if (c1 < 320) { p1 = Wv + (c1 - 256);               st1 = 64; }
        else if (c1 < 336) { p1 = g_Weff + (c1 - 320);           st1 = 16; }
        else               { p1 = Wi;                            st1 = 0;  }
    }

    unsigned long long a0[NP], a1[NP];
    #pragma unroll
    for (int j = 0; j < NP; j++) { a0[j] = 0ull; a1[j] = 0ull; }

    if (active) {
        #pragma unroll 2
        for (int k2 = 0; k2 < 64; k2++) {
            unsigned long long wA0 = pack2(p0[0]);
            unsigned long long wA1 = pack2(p0[st0]);
            unsigned long long wB0 = pack2(p1[0]);
            unsigned long long wB1 = pack2(p1[st1]);
            p0 += 2*st0; p1 += 2*st1;
            #pragma unroll
            for (int j = 0; j < NP; j++) {
                ulonglong2 q = xsQ[j][k2];
                fma2(a0[j], q.x, wA0);
                fma2(a0[j], q.y, wA1);
                fma2(a1[j], q.x, wB0);
                fma2(a1[j], q.y, wB1);
            }
        }
    }

    // epilogue part 1: Wv threads -> g_val (relu, float2 coalesced); Weff -> effS
    if (tid >= 128 && tid < 160) {
        int vc = tid - 128;                  // Wv float2-column 0..31
        float b0v = bv[2*vc], b1v = bv[2*vc + 1];
        #pragma unroll
        for (int j = 0; j < NP; j++) {
            float2 u0 = unpack2(a0[j]);      // col 2vc : nodes (2j, 2j+1)
            float2 u1 = unpack2(a1[j]);      // col 2vc+1
            float v00 = u0.x + b0v, v01 = u1.x + b1v;   // node 2j
            float v10 = u0.y + b0v, v11 = u1.y + b1v;   // node 2j+1
            reinterpret_cast<float2*>(g_val)[(node0 + 2*j)*32 + vc] =
                make_float2(v00 > 0.f ? v00 : 0.f, v01 > 0.f ? v01 : 0.f);
            reinterpret_cast<float2*>(g_val)[(node0 + 2*j + 1)*32 + vc] =
                make_float2(v10 > 0.f ? v10 : 0.f, v11 > 0.f ? v11 : 0.f);
        }
    } else if (tid >= 160 && tid < 168) {
        int s0 = 2*(tid - 160), s1 = s0 + 1;
        #pragma unroll
        for (int j = 0; j < NP; j++) {
            float2 u0 = unpack2(a0[j]);
            float2 u1 = unpack2(a1[j]);
            effS[2*j][s0]     = u0.x;  effS[2*j + 1][s0] = u0.y;
            effS[2*j][s1]     = u1.x;  effS[2*j + 1][s1] = u1.y;
        }
    }
    __syncthreads();

    // epilogue part 2: Wi threads -> beta via 8-lane butterfly
    if (tid < 128) {
        int s  = tid >> 3;             // = c0>>4
        int kp = (tid & 7)*2;          // = c0&15
        float b0 = bi[s*32 + kp], b1 = bi[s*32 + kp + 1];
        float beffv = g_beff[s];
        #pragma unroll
        for (int j = 0; j < NP; j++) {
            float2 u0 = unpack2(a0[j]);
            float2 u1 = unpack2(a1[j]);
            int n0 = 2*j, n1 = 2*j + 1;
            float c0v = (u0.x + b0)*mwS[n0][kp] + (u1.x + b1)*mwS[n0][kp + 1];
            float c1v = (u0.y + b0)*mwS[n1][kp] + (u1.y + b1)*mwS[n1][kp + 1];
            c0v += __shfl_xor_sync(FULL, c0v, 1);
            c0v += __shfl_xor_sync(FULL, c0v, 2);
            c0v += __shfl_xor_sync(FULL, c0v, 4);
            c1v += __shfl_xor_sync(FULL, c1v, 1);
            c1v += __shfl_xor_sync(FULL, c1v, 2);
            c1v += __shfl_xor_sync(FULL, c1v, 4);
            if ((tid & 7) == 0) {
                betaS[n0][s] = (c0v + effS[n0][s] + beffv) * (1.0f/32.0f);
                betaS[n1][s] = (c1v + effS[n1][s] + beffv) * (1.0f/32.0f);
            }
        }
    }
    __syncthreads();

    for (int idx = tid; idx < NB*16; idx += NTH) {
        int n = idx >> 4, s = idx & 15;
        g_beta[(node0 + n)*NSTEP + s] = betaS[n][s];
    }
    if (tid < NB) {
        float s = 0.f;
        #pragma unroll
        for (int k = 0; k < NSTEP; k++) s += betaS[tid][k];
        g_mean_beta[node0 + tid] = s * (1.0f/NSTEP);
    }
}

// ---------------- 3. keys + hist + chunk sums (+ zero srcCnt for this run) ----------------
__global__ void keyhist_kernel(const int* __restrict__ ei, const float* __restrict__ ew) {
    int e = blockIdx.x * blockDim.x + threadIdx.x;
    if (e >= E_EDGES) return;
    if (e < N_NODES) g_srcCnt[e] = 0;          // consumed later this run; prev run done
    if (e == 0) g_cand_cnt = 0;
    int lane = threadIdx.x & 31;
    int dst = ei[E_EDGES + e];
    float s = ew[e] * g_mean_beta[dst];
    s += 0.0f;                                 // -0 -> +0
    unsigned int k = fxform(s);
    g_keys[e] = k;
    unsigned int bin = k >> 16;
    unsigned int am = __activemask();
    unsigned int m = __match_any_sync(am, bin);
    if (lane == __ffs(m) - 1) atomicAdd(&g_hist16[bin], __popc(m));
    unsigned int ch = bin >> 10;
    unsigned int m2 = __match_any_sync(am, ch);
    if (lane == __ffs(m2) - 1) atomicAdd(&g_chunk[ch], __popc(m2));
}

// ---------------- 4. scan: chunk walk + warp-level suffix scan ----------------
__global__ __launch_bounds__(1024) void scanB_kernel() {
    __shared__ unsigned int s_chunk[64];
    __shared__ unsigned int s_wsum[32];
    __shared__ int          s_cstar;
    __shared__ unsigned int s_cumAbove;

    int tid = threadIdx.x, lane = tid & 31, w = tid >> 5;
    if (tid < 64) s_chunk[tid] = g_chunk[tid];
    __syncthreads();
    if (tid == 0) {
        unsigned int cum = 0; int cs = 0;
        for (int c = 63; c >= 0; c--) {
            unsigned int s = s_chunk[c];
            if (cum + s >= (unsigned)K_SEL) { cs = c; break; }
            cum += s;
        }
        s_cstar = cs; s_cumAbove = cum;
    }
    __syncthreads();
    int cs = s_cstar;
    unsigned int cumAbove = s_cumAbove;

    unsigned int v = g_hist16[cs*1024 + tid];
    unsigned int suf = v;
    #pragma unroll
    for (int off = 1; off < 32; off <<= 1) {
        unsigned int t2 = __shfl_down_sync(0xFFFFFFFFu, suf, off);
        if (lane + off < 32) suf += t2;
    }
    if (lane == 0) s_wsum[w] = suf;
    __syncthreads();
    if (w == 0) {
        unsigned int wv = s_wsum[lane];
        unsigned int ws = wv;
        #pragma unroll
        for (int off = 1; off < 32; off <<= 1) {
            unsigned int t2 = __shfl_down_sync(0xFFFFFFFFu, ws, off);
            if (lane + off < 32) ws += t2;
        }
        s_wsum[lane] = ws - wv;
    }
    __syncthreads();
    unsigned int incl  = suf + s_wsum[w];
    unsigned int above = cumAbove + incl - v;
    if (above < (unsigned)K_SEL && above + v >= (unsigned)K_SEL) {
        g_B = (unsigned)(cs*1024 + tid);
        g_R = K_SEL - (int)above;
    }
}

// ---------------- 5. flag winners + counts (+ zero hist for next run) ----------------
__global__ void flagcnt_kernel(const int* __restrict__ ei) {
    int e = blockIdx.x * blockDim.x + threadIdx.x;
    if (e >= E_EDGES) return;
    if (e < 65536) g_hist16[e] = 0u;           // scanB (prev launch) was last reader
    if (e < 64)    g_chunk[e]  = 0u;
    unsigned int k = g_keys[e];
    unsigned int B = g_B;
    unsigned int t16 = k >> 16;
    unsigned char f = 0;
    if (t16 > B) {
        f = 1;
        atomicAdd(&g_srcCnt[ei[e]], 1);
    } else if (t16 == B) {
        int p = atomicAdd(&g_cand_cnt, 1);
        if (p < CAND_CAP) { g_candK[p] = k; g_candE[p] = e; }
    }
    g_flags[e] = f;
}

// ---------------- 6. resolve ties + prefix-sum src counts ----------------
__global__ __launch_bounds__(1024) void resolve_kernel(const int* __restrict__ ei) {
    __shared__ unsigned int s_key[4096];
    __shared__ int          s_idx[4096];
    __shared__ unsigned int s_scan[1024];

    int C = g_cand_cnt; if (C > CAND_CAP) C = CAND_CAP;
    int R = g_R;
    if (C <= 4096) {
        for (int i = threadIdx.x; i < C; i += 1024) { s_key[i] = g_candK[i]; s_idx[i] = g_candE[i]; }
        __syncthreads();
        for (int i = threadIdx.x; i < C; i += 1024) {
            unsigned int ki = s_key[i]; int xi = s_idx[i];
            int rank = 0;
            for (int j = 0; j < C; j++) {
                unsigned int kj = s_key[j];
                rank += (kj > ki) || (kj == ki && s_idx[j] < xi);
            }
            if (rank < R) {
                g_flags[xi] = 1;
                atomicAdd(&g_srcCnt[ei[xi]], 1);
            }
        }
    } else {
        for (int i = threadIdx.x; i < C; i += 1024) {
            unsigned int ki = g_candK[i]; int xi = g_candE[i];
            int rank = 0;
            for (int j = 0; j < C; j++) {
                unsigned int kj = g_candK[j];
                rank += (kj > ki) || (kj == ki && g_candE[j] < xi);
            }
            if (rank < R) { g_flags[xi] = 1; atomicAdd(&g_srcCnt[ei[xi]], 1); }
        }
    }
    __threadfence();
    __syncthreads();

    int nbase = threadIdx.x * 10;
    int lsum = 0;
    int cnts[10];
    #pragma unroll
    for (int q = 0; q < 10; q++) {
        int n = nbase + q;
        cnts[q] = (n < N_NODES) ? g_srcCnt[n] : 0;
        lsum += cnts[q];
    }
    s_scan[threadIdx.x] = (unsigned)lsum;
    __syncthreads();
    for (int off = 1; off < 1024; off <<= 1) {
        unsigned int a = (threadIdx.x >= off) ? s_scan[threadIdx.x - off] : 0u;
        unsigned int b = s_scan[threadIdx.x];
        __syncthreads();
        s_scan[threadIdx.x] = b + a;
        __syncthreads();
    }
    int run = (int)s_scan[threadIdx.x] - lsum;
    #pragma unroll
    for (int q = 0; q < 10; q++) {
        int n = nbase + q;
        if (n < N_NODES) {
            g_srcBase[n] = run;
            g_srcCur[n]  = run;
            run += cnts[q];
        }
    }
}

// ---------------- 7. scatter ----------------
__global__ void scatter_kernel(const int* __restrict__ ei, const float* __restrict__ ew) {
    int e = blockIdx.x * blockDim.x + threadIdx.x;
    if (e >= E_EDGES) return;
    if (g_flags[e]) {
        int src = ei[e];
        int pos = atomicAdd(&g_srcCur[src], 1);
        g_sDst[pos] = ei[E_EDGES + e];
        g_sEw[pos]  = ew[e];
    }
}

// ---------------- 8. warp-per-src accumulate, packed exp ----------------
__global__ __launch_bounds__(1024) void acc_kernel(float* __restrict__ out) {
    const unsigned FULL = 0xFFFFFFFFu;
    int lane = threadIdx.x & 31;
    int gw = (blockIdx.x * blockDim.x + threadIdx.x) >> 5;
    int nwarps = (gridDim.x * blockDim.x) >> 5;
    int sA = lane >> 2;
    int sB = 8 + (lane >> 2);

    for (int src = gw; src < N_NODES; src += nwarps) {
        int cnt  = g_srcCnt[src];
        int base = g_srcBase[src];
        float a0 = 0.f, a1 = 0.f, ds = 0.f;
        int i = 0;
        for (; i + 2 <= cnt; i += 2) {
            int   d0 = g_sDst[base + i];
            int   d1 = g_sDst[base + i + 1];
            float w0 = g_sEw[base + i];
            float w1 = g_sEw[base + i + 1];
            float bval = (lane < 16) ? g_beta[d0*NSTEP + lane] * w0
                                     : g_beta[d1*NSTEP + (lane - 16)] * w1;
            float ex = __expf(bval);
            float e00 = __shfl_sync(FULL, ex, sA);
            float e01 = __shfl_sync(FULL, ex, sB);
            float e10 = __shfl_sync(FULL, ex, 16 + sA);
            float e11 = __shfl_sync(FULL, ex, 16 + sB);
            a0 = fmaf(e00, g_val[d0*64 + lane],      a0);
            a1 = fmaf(e01, g_val[d0*64 + 32 + lane], a1);
            a0 = fmaf(e10, g_val[d1*64 + lane],      a0);
            a1 = fmaf(e11, g_val[d1*64 + 32 + lane], a1);
            ds += ex;
        }
        if (i < cnt) {
            int   d0 = g_sDst[base + i];
            float w0 = g_sEw[base + i];
            float ex0 = 0.f;
            if (lane < 16) ex0 = __expf(g_beta[d0*NSTEP + lane] * w0);
            float e00 = __shfl_sync(FULL, ex0, sA);
            float e01 = __shfl_sync(FULL, ex0, sB);
            a0 = fmaf(e00, g_val[d0*64 + lane],      a0);
            a1 = fmaf(e01, g_val[d0*64 + 32 + lane], a1);
            ds += ex0;
        }
        float dA = __shfl_sync(FULL, ds, sA) + __shfl_sync(FULL, ds, 16 + sA) + 1e-16f;
        float dB = __shfl_sync(FULL, ds, sB) + __shfl_sync(FULL, ds, 16 + sB) + 1e-16f;
        out[src*64 + lane]      = a0 / dA;
        out[src*64 + 32 + lane] = a1 / dB;
    }
}

// ---------------- launch ----------------
extern "C" void kernel_launch(void* const* d_in, const int* in_sizes, int n_in,
                              void* d_out, int out_size) {
    const float* x   = (const float*)d_in[0];
    const float* p_t = (const float*)d_in[1];
    const int*   ei  = (const int*)  d_in[2];
    const float* ew  = (const float*)d_in[3];
    const float* Wv  = (const float*)d_in[4];
    const float* bv  = (const float*)d_in[5];
    const float* Wi  = (const float*)d_in[6];
    const float* bi  = (const float*)d_in[7];
    const float* mw  = (const float*)d_in[8];
    float* out = (float*)d_out;

    const int EB = (E_EDGES + 255)/256;

    weff_kernel<<<16, 128>>>(Wi, bi, p_t);
    node_kernel<<<N_NODES/NB, NTH>>>(x, Wv, bv, Wi, bi, mw);
    keyhist_kernel<<<EB, 256>>>(ei, ew);
    scanB_kernel<<<1, 1024>>>();
    flagcnt_kernel<<<EB, 256>>>(ei);
    resolve_kernel<<<1, 1024>>>(ei);
    scatter_kernel<<<EB, 256>>>(ei, ew);
    acc_kernel<<<320, 1024>>>(out);
}